// round 8
// baseline (speedup 1.0000x reference)
#include <cuda_runtime.h>
#include <cuda_bf16.h>
#include <math.h>
#include <stdint.h>

// Problem constants
#define T_   256
#define B_   128
#define F_   1024
#define U_   512
#define G4_  2048   // 4*U
#define CODES_ 1024
#define ROWS_ 32768 // T*B

#define RBLK 128    // persistent recurrence blocks
#define KC   32     // recurrence K chunk
#define HPITCH 130  // Hs row pitch (even -> 8B-aligned batch pairs)

// Tensor GEMM tile
#define BKT  32
#define APITCH 40
#define BPITCH 136

#define SA_ELEM (128 * APITCH)
#define SB_ELEM (BKT * BPITCH)
#define STAGE_ELEM (2 * SA_ELEM + 2 * SB_ELEM)
#define GEMM_SMEM (2 * STAGE_ELEM * 2)

// ---------------------------------------------------------------------------
// Scratch
// ---------------------------------------------------------------------------
__device__ float g_xz   [(size_t)ROWS_ * G4_];
__device__ float g_hseq [(size_t)ROWS_ * U_];
__device__ float g_h0   [B_ * U_];
__device__ float g_Wrec4[(size_t)U_ * G4_];
__device__ float g_b4   [G4_];
__device__ unsigned g_bar;

__device__ __nv_bfloat16 g_xh [(size_t)ROWS_ * F_];
__device__ __nv_bfloat16 g_xl [(size_t)ROWS_ * F_];
__device__ __nv_bfloat16 g_Wih[(size_t)F_ * G4_];
__device__ __nv_bfloat16 g_Wil[(size_t)F_ * G4_];
__device__ __nv_bfloat16 g_Wdh[(size_t)U_ * CODES_];
__device__ __nv_bfloat16 g_Wdl[(size_t)U_ * CODES_];
__device__ __nv_bfloat16 g_hh [(size_t)ROWS_ * U_];
__device__ __nv_bfloat16 g_hl [(size_t)ROWS_ * U_];

// ---------------------------------------------------------------------------
// Helpers
// ---------------------------------------------------------------------------
__device__ __forceinline__ uint32_t smem_u32(const void* p) {
    return (uint32_t)__cvta_generic_to_shared(p);
}
__device__ __forceinline__ void cpa16(uint32_t dst, const void* src) {
    asm volatile("cp.async.cg.shared.global [%0], [%1], 16;\n" :: "r"(dst), "l"(src));
}
__device__ __forceinline__ void cpa_commit() { asm volatile("cp.async.commit_group;\n" ::); }
__device__ __forceinline__ void cpa_wait0()  { asm volatile("cp.async.wait_group 0;\n" ::); }
__device__ __forceinline__ void ldsm_x4(uint32_t& r0, uint32_t& r1, uint32_t& r2, uint32_t& r3, uint32_t a) {
    asm volatile("ldmatrix.sync.aligned.m8n8.x4.shared.b16 {%0,%1,%2,%3},[%4];"
                 : "=r"(r0), "=r"(r1), "=r"(r2), "=r"(r3) : "r"(a));
}
__device__ __forceinline__ void ldsm_x4t(uint32_t& r0, uint32_t& r1, uint32_t& r2, uint32_t& r3, uint32_t a) {
    asm volatile("ldmatrix.sync.aligned.m8n8.x4.trans.shared.b16 {%0,%1,%2,%3},[%4];"
                 : "=r"(r0), "=r"(r1), "=r"(r2), "=r"(r3) : "r"(a));
}
__device__ __forceinline__ void mma_bf16(float c[4], const uint32_t a[4], const uint32_t b[2]) {
    asm volatile(
        "mma.sync.aligned.m16n8k16.row.col.f32.bf16.bf16.f32 "
        "{%0,%1,%2,%3},{%4,%5,%6,%7},{%8,%9},{%0,%1,%2,%3};"
        : "+f"(c[0]), "+f"(c[1]), "+f"(c[2]), "+f"(c[3])
        : "r"(a[0]), "r"(a[1]), "r"(a[2]), "r"(a[3]), "r"(b[0]), "r"(b[1]));
}
// Packed fp32x2 FMA: acc = a*b + acc, two fp32 lanes per instruction.
__device__ __forceinline__ void fma2(unsigned long long& acc,
                                     unsigned long long a, unsigned long long b) {
    asm("fma.rn.f32x2 %0, %1, %2, %0;" : "+l"(acc) : "l"(a), "l"(b));
}

// ---------------------------------------------------------------------------
// Pre-pass kernels
// ---------------------------------------------------------------------------
__global__ void reorder_gates(const float* __restrict__ W, float* __restrict__ W4, int total) {
    int idx = blockIdx.x * blockDim.x + threadIdx.x;
    if (idx >= total) return;
    int col = idx & (G4_ - 1);
    int k   = idx >> 11;
    W4[idx] = W[(size_t)k * G4_ + (col & 3) * U_ + (col >> 2)];
}

__global__ void reorder_split(const float* __restrict__ W,
                              __nv_bfloat16* __restrict__ hi,
                              __nv_bfloat16* __restrict__ lo, int total) {
    int idx = blockIdx.x * blockDim.x + threadIdx.x;
    if (idx >= total) return;
    int col = idx & (G4_ - 1);
    int k   = idx >> 11;
    float v = W[(size_t)k * G4_ + (col & 3) * U_ + (col >> 2)];
    __nv_bfloat16 h = __float2bfloat16(v);
    hi[idx] = h;
    lo[idx] = __float2bfloat16(v - __bfloat162float(h));
}

__global__ void convert_split(const float* __restrict__ src,
                              __nv_bfloat16* __restrict__ hi,
                              __nv_bfloat16* __restrict__ lo, int n4) {
    int idx = blockIdx.x * blockDim.x + threadIdx.x;
    if (idx >= n4) return;
    float4 v = *(const float4*)(src + (size_t)idx * 4);
    __nv_bfloat16 h0 = __float2bfloat16(v.x), h1 = __float2bfloat16(v.y);
    __nv_bfloat16 h2 = __float2bfloat16(v.z), h3 = __float2bfloat16(v.w);
    *(__nv_bfloat162*)(hi + (size_t)idx * 4)     = __halves2bfloat162(h0, h1);
    *(__nv_bfloat162*)(hi + (size_t)idx * 4 + 2) = __halves2bfloat162(h2, h3);
    *(__nv_bfloat162*)(lo + (size_t)idx * 4)     =
        __halves2bfloat162(__float2bfloat16(v.x - __bfloat162float(h0)),
                           __float2bfloat16(v.y - __bfloat162float(h1)));
    *(__nv_bfloat162*)(lo + (size_t)idx * 4 + 2) =
        __halves2bfloat162(__float2bfloat16(v.z - __bfloat162float(h2)),
                           __float2bfloat16(v.w - __bfloat162float(h3)));
}

__global__ void convert_mask(const float* __restrict__ hseq,
                             const float* __restrict__ mask,
                             __nv_bfloat16* __restrict__ hi,
                             __nv_bfloat16* __restrict__ lo, int n4) {
    int idx = blockIdx.x * blockDim.x + threadIdx.x;
    if (idx >= n4) return;
    float m = mask[(idx * 4) >> 9];
    float4 v = *(const float4*)(hseq + (size_t)idx * 4);
    v.x *= m; v.y *= m; v.z *= m; v.w *= m;
    __nv_bfloat16 h0 = __float2bfloat16(v.x), h1 = __float2bfloat16(v.y);
    __nv_bfloat16 h2 = __float2bfloat16(v.z), h3 = __float2bfloat16(v.w);
    *(__nv_bfloat162*)(hi + (size_t)idx * 4)     = __halves2bfloat162(h0, h1);
    *(__nv_bfloat162*)(hi + (size_t)idx * 4 + 2) = __halves2bfloat162(h2, h3);
    *(__nv_bfloat162*)(lo + (size_t)idx * 4)     =
        __halves2bfloat162(__float2bfloat16(v.x - __bfloat162float(h0)),
                           __float2bfloat16(v.y - __bfloat162float(h1)));
    *(__nv_bfloat162*)(lo + (size_t)idx * 4 + 2) =
        __halves2bfloat162(__float2bfloat16(v.z - __bfloat162float(h2)),
                           __float2bfloat16(v.w - __bfloat162float(h3)));
}

__global__ void init_kernel(const float* __restrict__ b_lstm,
                            float* __restrict__ b4,
                            float* __restrict__ h0,
                            unsigned* __restrict__ bar) {
    int idx = blockIdx.x * blockDim.x + threadIdx.x;
    if (idx == 0) *bar = 0u;
    if (idx < G4_) b4[idx] = b_lstm[(idx & 3) * U_ + (idx >> 2)];
    if (idx < B_ * U_) h0[idx] = 0.0f;
}

// ---------------------------------------------------------------------------
// Tensor-core GEMM (3-term bf16 hi/lo). FROZEN from R7 (passing config).
// ---------------------------------------------------------------------------
__global__ __launch_bounds__(256, 2) void tgemm2(
    const __nv_bfloat16* __restrict__ Ah, const __nv_bfloat16* __restrict__ Al,
    const __nv_bfloat16* __restrict__ Bh, const __nv_bfloat16* __restrict__ Bl,
    const float* __restrict__ bias, float* __restrict__ C,
    int M, int N, int K, int relu)
{
    extern __shared__ __nv_bfloat16 ts[];

    int tid  = threadIdx.x;
    int warp = tid >> 5, lane = tid & 31;
    int wm = warp >> 1, wn = warp & 1;
    int m0 = blockIdx.y * 128, n0 = blockIdx.x * 128;

    int a1r = tid >> 2,         a1s = tid & 3;
    int a2r = (tid + 256) >> 2, a2s = (tid + 256) & 3;
    int b1r = tid >> 4,         b1s = tid & 15;
    int b2r = (tid + 256) >> 4, b2s = (tid + 256) & 15;

    float acc[2][8][4];
    #pragma unroll
    for (int i = 0; i < 2; i++)
        #pragma unroll
        for (int j = 0; j < 8; j++)
            #pragma unroll
            for (int q = 0; q < 4; q++) acc[i][j][q] = 0.0f;

    int a_r = (lane & 15);
    int a_c = (lane >> 4) * 8;
    int aoffA = (wm * 32 + a_r) * APITCH + a_c;
    int aoffB = a_r * BPITCH + wn * 64 + a_c;

    int KT = K / BKT;

    auto load_stage = [&](int kt, int s) {
        __nv_bfloat16* st = ts + s * STAGE_ELEM;
        __nv_bfloat16* sAh = st;
        __nv_bfloat16* sAl = st + SA_ELEM;
        __nv_bfloat16* sBh = st + 2 * SA_ELEM;
        __nv_bfloat16* sBl = st + 2 * SA_ELEM + SB_ELEM;
        int k0 = kt * BKT;
        const __nv_bfloat16* gAh = Ah + (size_t)m0 * K + k0;
        const __nv_bfloat16* gAl = Al + (size_t)m0 * K + k0;
        const __nv_bfloat16* gBh = Bh + (size_t)k0 * N + n0;
        const __nv_bfloat16* gBl = Bl + (size_t)k0 * N + n0;
        cpa16(smem_u32(sAh + a1r * APITCH + a1s * 8), gAh + (size_t)a1r * K + a1s * 8);
        cpa16(smem_u32(sAh + a2r * APITCH + a2s * 8), gAh + (size_t)a2r * K + a2s * 8);
        cpa16(smem_u32(sAl + a1r * APITCH + a1s * 8), gAl + (size_t)a1r * K + a1s * 8);
        cpa16(smem_u32(sAl + a2r * APITCH + a2s * 8), gAl + (size_t)a2r * K + a2s * 8);
        cpa16(smem_u32(sBh + b1r * BPITCH + b1s * 8), gBh + (size_t)b1r * N + b1s * 8);
        cpa16(smem_u32(sBh + b2r * BPITCH + b2s * 8), gBh + (size_t)b2r * N + b2s * 8);
        cpa16(smem_u32(sBl + b1r * BPITCH + b1s * 8), gBl + (size_t)b1r * N + b1s * 8);
        cpa16(smem_u32(sBl + b2r * BPITCH + b2s * 8), gBl + (size_t)b2r * N + b2s * 8);
    };

    load_stage(0, 0);
    cpa_commit();
    cpa_wait0();
    __syncthreads();

    for (int kt = 0; kt < KT; kt++) {
        int cur = kt & 1;
        if (kt + 1 < KT) {
            load_stage(kt + 1, cur ^ 1);
            cpa_commit();
        }

        __nv_bfloat16* st = ts + cur * STAGE_ELEM;
        uint32_t aAh = smem_u32(st + aoffA);
        uint32_t aAl = smem_u32(st + SA_ELEM + aoffA);
        uint32_t aBh = smem_u32(st + 2 * SA_ELEM + aoffB);
        uint32_t aBl = smem_u32(st + 2 * SA_ELEM + SB_ELEM + aoffB);

        #pragma unroll
        for (int kk = 0; kk < 2; kk++) {
            uint32_t Ahf[2][4], Alf[2][4];
            #pragma unroll
            for (int mt = 0; mt < 2; mt++) {
                uint32_t off = (mt * 16) * APITCH * 2 + kk * 16 * 2;
                ldsm_x4(Ahf[mt][0], Ahf[mt][1], Ahf[mt][2], Ahf[mt][3], aAh + off);
                ldsm_x4(Alf[mt][0], Alf[mt][1], Alf[mt][2], Alf[mt][3], aAl + off);
            }
            uint32_t Bhf[8][2], Blf[8][2];
            #pragma unroll
            for (int p = 0; p < 4; p++) {
                uint32_t off = (kk * 16) * BPITCH * 2 + p * 16 * 2;
                ldsm_x4t(Bhf[2*p][0], Bhf[2*p][1], Bhf[2*p+1][0], Bhf[2*p+1][1], aBh + off);
                ldsm_x4t(Blf[2*p][0], Blf[2*p][1], Blf[2*p+1][0], Blf[2*p+1][1], aBl + off);
            }
            #pragma unroll
            for (int mt = 0; mt < 2; mt++)
                #pragma unroll
                for (int nt = 0; nt < 8; nt++) {
                    mma_bf16(acc[mt][nt], Ahf[mt], Bhf[nt]);
                    mma_bf16(acc[mt][nt], Ahf[mt], Blf[nt]);
                    mma_bf16(acc[mt][nt], Alf[mt], Bhf[nt]);
                }
        }

        if (kt + 1 < KT) cpa_wait0();
        __syncthreads();
    }

    int crow = lane >> 2;
    int ccol = (lane & 3) * 2;
    #pragma unroll
    for (int mt = 0; mt < 2; mt++) {
        int r0 = m0 + wm * 32 + mt * 16 + crow;
        #pragma unroll
        for (int nt = 0; nt < 8; nt++) {
            int cglob = n0 + wn * 64 + nt * 8 + ccol;
            float b0 = bias[cglob], b1 = bias[cglob + 1];
            float2 v0 = { acc[mt][nt][0] + b0, acc[mt][nt][1] + b1 };
            float2 v1 = { acc[mt][nt][2] + b0, acc[mt][nt][3] + b1 };
            if (relu) {
                v0.x = fmaxf(v0.x, 0.f); v0.y = fmaxf(v0.y, 0.f);
                v1.x = fmaxf(v1.x, 0.f); v1.y = fmaxf(v1.y, 0.f);
            }
            *(float2*)(C + (size_t)r0 * N + cglob)       = v0;
            *(float2*)(C + (size_t)(r0 + 8) * N + cglob) = v1;
        }
    }
}

// ---------------------------------------------------------------------------
// Persistent LSTM recurrence with packed f32x2 FMA.
// Block j owns units [j*4, j*4+4) (gate-cols [j*16, j*16+16)).
// Thread (tx, ty): unit j*4+tx, batches {2ty, 2ty+1} packed into f32x2 lanes.
// SMEM: Ws2 = W_rec slice with each weight DUPLICATED into both f32x2 lanes
// (512x16 x 8B = 64KB, loaded once); Hs = h chunk [KC][HPITCH] floats.
// Inner kk: 2x LDS.128 (4 dup'd gates) + 1x LDS.64 (batch pair, IS the f32x2
// operand) + 4x fma.rn.f32x2  (was 3 LDS + 8 scalar FFMA).
// ---------------------------------------------------------------------------
__global__ __launch_bounds__(256) void lstm_persistent(
    const float* __restrict__ h0,
    const float* __restrict__ xz,
    const float* __restrict__ Wrec,
    float* hseq,
    unsigned* bar)
{
    extern __shared__ char smemc[];
    unsigned long long* Ws2 = (unsigned long long*)smemc;     // [512][16] dup'd
    float* Hs = (float*)(smemc + 512 * 16 * 8);               // [KC][HPITCH]

    int tid = threadIdx.x;
    int blk = blockIdx.x;
    int n0 = blk * 16;
    int tx = tid & 3;
    int ty = tid >> 2;
    int u  = blk * 4 + tx;

    // Cache W_rec slice, duplicated into both f32x2 lanes (once)
    for (int l = tid; l < 512 * 16; l += 256) {
        int row = l >> 4, g = l & 15;
        unsigned long long d = (unsigned long long)__float_as_uint(
            Wrec[(size_t)row * G4_ + n0 + g]);
        Ws2[l] = d | (d << 32);
    }

    float creg0 = 0.0f, creg1 = 0.0f;
    const float* hp = h0;

    for (int t = 0; t < T_; t++) {
        unsigned long long acc2[4];
        #pragma unroll
        for (int j = 0; j < 4; j++) acc2[j] = 0ull;

        for (int k0 = 0; k0 < U_; k0 += KC) {
            // stage h chunk transposed: Hs[kk][b], even pitch for 8B pairs
            #pragma unroll
            for (int i = 0; i < 4; i++) {
                int l = tid + i * 256;
                int b = l >> 3, k4 = l & 7;
                float4 v = __ldcg((const float4*)(hp + (size_t)b * U_ + k0 + k4 * 4));
                Hs[(k4 * 4 + 0) * HPITCH + b] = v.x;
                Hs[(k4 * 4 + 1) * HPITCH + b] = v.y;
                Hs[(k4 * 4 + 2) * HPITCH + b] = v.z;
                Hs[(k4 * 4 + 3) * HPITCH + b] = v.w;
            }
            __syncthreads();

            #pragma unroll
            for (int kk = 0; kk < KC; kk++) {
                const unsigned long long* wrow = &Ws2[(k0 + kk) * 16 + tx * 4];
                ulonglong2 wA = *(const ulonglong2*)(wrow);      // gates 0,1 dup'd
                ulonglong2 wB = *(const ulonglong2*)(wrow + 2);  // gates 2,3 dup'd
                unsigned long long h2 =
                    *(const unsigned long long*)&Hs[kk * HPITCH + ty * 2];
                fma2(acc2[0], h2, wA.x);
                fma2(acc2[1], h2, wA.y);
                fma2(acc2[2], h2, wB.x);
                fma2(acc2[3], h2, wB.y);
            }
            __syncthreads();
        }

        // unpack lanes: lane0 = batch 2ty, lane1 = batch 2ty+1
        float a0[4], a1[4];
        #pragma unroll
        for (int j = 0; j < 4; j++) {
            a0[j] = __uint_as_float((unsigned)(acc2[j] & 0xffffffffull));
            a1[j] = __uint_as_float((unsigned)(acc2[j] >> 32));
        }

        #pragma unroll
        for (int i = 0; i < 2; i++) {
            int b = ty * 2 + i;
            const float* xzp = xz + ((size_t)t * B_ + b) * G4_ + n0 + tx * 4;
            float zi = (i ? a1[0] : a0[0]) + xzp[0];
            float zf = (i ? a1[1] : a0[1]) + xzp[1];
            float zg = (i ? a1[2] : a0[2]) + xzp[2];
            float zo = (i ? a1[3] : a0[3]) + xzp[3];
            float ig = 1.0f / (1.0f + expf(-zi));
            float fg = 1.0f / (1.0f + expf(-zf));
            float gg = tanhf(zg);
            float og = 1.0f / (1.0f + expf(-zo));
            float cp = i ? creg1 : creg0;
            float cn = fg * cp + ig * gg;
            if (i) creg1 = cn; else creg0 = cn;
            hseq[((size_t)t * B_ + b) * U_ + u] = og * tanhf(cn);
        }

        __threadfence();
        __syncthreads();
        if (tid == 0) {
            atomicAdd(bar, 1u);
            unsigned target = (unsigned)RBLK * (unsigned)(t + 1);
            while (*(volatile unsigned*)bar < target) {}
        }
        __syncthreads();

        hp = hseq + (size_t)t * B_ * U_;
    }
}

// ---------------------------------------------------------------------------
// In-place row softmax (1024 cols, one block/row).
// ---------------------------------------------------------------------------
__global__ __launch_bounds__(256) void softmax_kernel(float* __restrict__ out) {
    __shared__ float red[8];
    int tid = threadIdx.x;
    float* p = out + (size_t)blockIdx.x * CODES_;

    float4 v = *(float4*)(p + tid * 4);
    float m = fmaxf(fmaxf(v.x, v.y), fmaxf(v.z, v.w));
    #pragma unroll
    for (int o = 16; o > 0; o >>= 1) m = fmaxf(m, __shfl_xor_sync(0xFFFFFFFFu, m, o));
    if ((tid & 31) == 0) red[tid >> 5] = m;
    __syncthreads();
    float bm = red[0];
    #pragma unroll
    for (int i = 1; i < 8; i++) bm = fmaxf(bm, red[i]);
    __syncthreads();

    v.x = expf(v.x - bm); v.y = expf(v.y - bm);
    v.z = expf(v.z - bm); v.w = expf(v.w - bm);
    float s = v.x + v.y + v.z + v.w;
    #pragma unroll
    for (int o = 16; o > 0; o >>= 1) s += __shfl_xor_sync(0xFFFFFFFFu, s, o);
    if ((tid & 31) == 0) red[tid >> 5] = s;
    __syncthreads();
    float bs = red[0];
    #pragma unroll
    for (int i = 1; i < 8; i++) bs += red[i];
    float inv = 1.0f / bs;
    v.x *= inv; v.y *= inv; v.z *= inv; v.w *= inv;
    *(float4*)(p + tid * 4) = v;
}

// ---------------------------------------------------------------------------
// Launch
// ---------------------------------------------------------------------------
extern "C" void kernel_launch(void* const* d_in, const int* in_sizes, int n_in,
                              void* d_out, int out_size) {
    const float* x       = (const float*)d_in[0];
    const float* mask    = (const float*)d_in[1];
    const float* W_in    = (const float*)d_in[2];
    const float* W_rec   = (const float*)d_in[3];
    const float* b_lstm  = (const float*)d_in[4];
    const float* W_dense = (const float*)d_in[5];
    const float* b_dense = (const float*)d_in[6];
    float* out = (float*)d_out;

    float *xz, *hseq, *h0, *Wrec4, *b4;
    unsigned* bar;
    __nv_bfloat16 *xh, *xl, *Wih, *Wil, *Wdh, *Wdl, *hh, *hl;
    cudaGetSymbolAddress((void**)&xz,    g_xz);
    cudaGetSymbolAddress((void**)&hseq,  g_hseq);
    cudaGetSymbolAddress((void**)&h0,    g_h0);
    cudaGetSymbolAddress((void**)&Wrec4, g_Wrec4);
    cudaGetSymbolAddress((void**)&b4,    g_b4);
    cudaGetSymbolAddress((void**)&bar,   g_bar);
    cudaGetSymbolAddress((void**)&xh,    g_xh);
    cudaGetSymbolAddress((void**)&xl,    g_xl);
    cudaGetSymbolAddress((void**)&Wih,   g_Wih);
    cudaGetSymbolAddress((void**)&Wil,   g_Wil);
    cudaGetSymbolAddress((void**)&Wdh,   g_Wdh);
    cudaGetSymbolAddress((void**)&Wdl,   g_Wdl);
    cudaGetSymbolAddress((void**)&hh,    g_hh);
    cudaGetSymbolAddress((void**)&hl,    g_hl);

    int lstm_smem = 512 * 16 * 8 + KC * HPITCH * (int)sizeof(float);
    cudaFuncSetAttribute(lstm_persistent,
                         cudaFuncAttributeMaxDynamicSharedMemorySize, lstm_smem);
    cudaFuncSetAttribute(tgemm2,
                         cudaFuncAttributeMaxDynamicSharedMemorySize, GEMM_SMEM);

    // Pre-passes
    reorder_gates<<<(U_ * G4_ + 255) / 256, 256>>>(W_rec, Wrec4, U_ * G4_);
    reorder_split<<<(F_ * G4_ + 255) / 256, 256>>>(W_in, Wih, Wil, F_ * G4_);
    convert_split<<<(U_ * CODES_ / 4 + 255) / 256, 256>>>(W_dense, Wdh, Wdl, U_ * CODES_ / 4);
    convert_split<<<((int)((size_t)ROWS_ * F_ / 4) + 255) / 256, 256>>>(x, xh, xl, (int)((size_t)ROWS_ * F_ / 4));
    init_kernel<<<(B_ * U_ + 255) / 256, 256>>>(b_lstm, b4, h0, bar);

    // Phase 1: xz = x @ Win4 + b4 (tensor, pre-split operands)
    tgemm2<<<dim3(G4_ / 128, ROWS_ / 128), 256, GEMM_SMEM>>>(
        xh, xl, Wih, Wil, b4, xz, ROWS_, G4_, F_, 0);

    // Phase 2: persistent recurrence (f32x2)
    lstm_persistent<<<RBLK, 256, lstm_smem>>>(h0, xz, Wrec4, hseq, bar);

    // Phase 2.5: masked h -> bf16 hi/lo
    convert_mask<<<((int)((size_t)ROWS_ * U_ / 4) + 255) / 256, 256>>>(
        hseq, mask, hh, hl, (int)((size_t)ROWS_ * U_ / 4));

    // Phase 3: logits = relu(masked_h @ W_dense + b_dense)
    tgemm2<<<dim3(CODES_ / 128, ROWS_ / 128), 256, GEMM_SMEM>>>(
        hh, hl, Wdh, Wdl, b_dense, out, ROWS_, CODES_, U_, 1);

    // Phase 4: softmax
    softmax_kernel<<<ROWS_, 256>>>(out);
}

// round 9
// speedup vs baseline: 1.2972x; 1.2972x over previous
#include <cuda_runtime.h>
#include <cuda_bf16.h>
#include <math.h>
#include <stdint.h>

// Problem constants
#define T_   256
#define B_   128
#define F_   1024
#define U_   512
#define G4_  2048   // 4*U
#define CODES_ 1024
#define ROWS_ 32768 // T*B

#define RBLK 128    // fused persistent blocks (1/SM guaranteed by 64K-reg cap)
#define KC   32     // recurrence K chunk

// Tensor GEMM tile
#define BKT  32
#define APITCH 40
#define BPITCH 136
#define SA_ELEM (128 * APITCH)
#define SB_ELEM (BKT * BPITCH)
#define STAGE_ELEM (2 * SA_ELEM + 2 * SB_ELEM)
#define GEMM_SMEM (2 * STAGE_ELEM * 2)          // 75776 B

// Fused kernel smem layout (bytes)
#define FS_WS   GEMM_SMEM                        // 75776: W_rec slice (512x16 f32)
#define FS_HS   (FS_WS + 512 * 16 * 4)           // 108544: Hs (KC x 129 f32)
#define FS_TILE (FS_HS + KC * 129 * 4)           // 125056: tile broadcast slot
#define FUSED_SMEM (FS_TILE + 16)                // 125072

#define P1_TILES (T_ * (G4_ / 128))              // 4096 tiles, 16 per timestep

#define BARR1 asm volatile("bar.sync 1, 256;" ::: "memory")
#define BARR2 asm volatile("bar.sync 2, 256;" ::: "memory")

// ---------------------------------------------------------------------------
// Scratch
// ---------------------------------------------------------------------------
__device__ float g_xz   [(size_t)ROWS_ * G4_];
__device__ float g_hseq [(size_t)ROWS_ * U_];
__device__ float g_h0   [B_ * U_];
__device__ float g_Wrec4[(size_t)U_ * G4_];
__device__ float g_b4   [G4_];
__device__ unsigned g_bar;
__device__ unsigned g_q;
__device__ unsigned g_ready[T_];

__device__ __nv_bfloat16 g_xh [(size_t)ROWS_ * F_];
__device__ __nv_bfloat16 g_xl [(size_t)ROWS_ * F_];
__device__ __nv_bfloat16 g_Wih[(size_t)F_ * G4_];
__device__ __nv_bfloat16 g_Wil[(size_t)F_ * G4_];
__device__ __nv_bfloat16 g_Wdh[(size_t)U_ * CODES_];
__device__ __nv_bfloat16 g_Wdl[(size_t)U_ * CODES_];
__device__ __nv_bfloat16 g_hh [(size_t)ROWS_ * U_];
__device__ __nv_bfloat16 g_hl [(size_t)ROWS_ * U_];

// ---------------------------------------------------------------------------
// Helpers
// ---------------------------------------------------------------------------
__device__ __forceinline__ uint32_t smem_u32(const void* p) {
    return (uint32_t)__cvta_generic_to_shared(p);
}
__device__ __forceinline__ void cpa16(uint32_t dst, const void* src) {
    asm volatile("cp.async.cg.shared.global [%0], [%1], 16;\n" :: "r"(dst), "l"(src));
}
__device__ __forceinline__ void cpa_commit() { asm volatile("cp.async.commit_group;\n" ::); }
__device__ __forceinline__ void cpa_wait0()  { asm volatile("cp.async.wait_group 0;\n" ::); }
__device__ __forceinline__ void ldsm_x4(uint32_t& r0, uint32_t& r1, uint32_t& r2, uint32_t& r3, uint32_t a) {
    asm volatile("ldmatrix.sync.aligned.m8n8.x4.shared.b16 {%0,%1,%2,%3},[%4];"
                 : "=r"(r0), "=r"(r1), "=r"(r2), "=r"(r3) : "r"(a));
}
__device__ __forceinline__ void ldsm_x4t(uint32_t& r0, uint32_t& r1, uint32_t& r2, uint32_t& r3, uint32_t a) {
    asm volatile("ldmatrix.sync.aligned.m8n8.x4.trans.shared.b16 {%0,%1,%2,%3},[%4];"
                 : "=r"(r0), "=r"(r1), "=r"(r2), "=r"(r3) : "r"(a));
}
__device__ __forceinline__ void mma_bf16(float c[4], const uint32_t a[4], const uint32_t b[2]) {
    asm volatile(
        "mma.sync.aligned.m16n8k16.row.col.f32.bf16.bf16.f32 "
        "{%0,%1,%2,%3},{%4,%5,%6,%7},{%8,%9},{%0,%1,%2,%3};"
        : "+f"(c[0]), "+f"(c[1]), "+f"(c[2]), "+f"(c[3])
        : "r"(a[0]), "r"(a[1]), "r"(a[2]), "r"(a[3]), "r"(b[0]), "r"(b[1]));
}

// ---------------------------------------------------------------------------
// Pre-pass kernels
// ---------------------------------------------------------------------------
__global__ void reorder_gates(const float* __restrict__ W, float* __restrict__ W4, int total) {
    int idx = blockIdx.x * blockDim.x + threadIdx.x;
    if (idx >= total) return;
    int col = idx & (G4_ - 1);
    int k   = idx >> 11;
    W4[idx] = W[(size_t)k * G4_ + (col & 3) * U_ + (col >> 2)];
}

__global__ void reorder_split(const float* __restrict__ W,
                              __nv_bfloat16* __restrict__ hi,
                              __nv_bfloat16* __restrict__ lo, int total) {
    int idx = blockIdx.x * blockDim.x + threadIdx.x;
    if (idx >= total) return;
    int col = idx & (G4_ - 1);
    int k   = idx >> 11;
    float v = W[(size_t)k * G4_ + (col & 3) * U_ + (col >> 2)];
    __nv_bfloat16 h = __float2bfloat16(v);
    hi[idx] = h;
    lo[idx] = __float2bfloat16(v - __bfloat162float(h));
}

__global__ void convert_split(const float* __restrict__ src,
                              __nv_bfloat16* __restrict__ hi,
                              __nv_bfloat16* __restrict__ lo, int n4) {
    int idx = blockIdx.x * blockDim.x + threadIdx.x;
    if (idx >= n4) return;
    float4 v = *(const float4*)(src + (size_t)idx * 4);
    __nv_bfloat16 h0 = __float2bfloat16(v.x), h1 = __float2bfloat16(v.y);
    __nv_bfloat16 h2 = __float2bfloat16(v.z), h3 = __float2bfloat16(v.w);
    *(__nv_bfloat162*)(hi + (size_t)idx * 4)     = __halves2bfloat162(h0, h1);
    *(__nv_bfloat162*)(hi + (size_t)idx * 4 + 2) = __halves2bfloat162(h2, h3);
    *(__nv_bfloat162*)(lo + (size_t)idx * 4)     =
        __halves2bfloat162(__float2bfloat16(v.x - __bfloat162float(h0)),
                           __float2bfloat16(v.y - __bfloat162float(h1)));
    *(__nv_bfloat162*)(lo + (size_t)idx * 4 + 2) =
        __halves2bfloat162(__float2bfloat16(v.z - __bfloat162float(h2)),
                           __float2bfloat16(v.w - __bfloat162float(h3)));
}

__global__ void convert_mask(const float* __restrict__ hseq,
                             const float* __restrict__ mask,
                             __nv_bfloat16* __restrict__ hi,
                             __nv_bfloat16* __restrict__ lo, int n4) {
    int idx = blockIdx.x * blockDim.x + threadIdx.x;
    if (idx >= n4) return;
    float m = mask[(idx * 4) >> 9];
    float4 v = *(const float4*)(hseq + (size_t)idx * 4);
    v.x *= m; v.y *= m; v.z *= m; v.w *= m;
    __nv_bfloat16 h0 = __float2bfloat16(v.x), h1 = __float2bfloat16(v.y);
    __nv_bfloat16 h2 = __float2bfloat16(v.z), h3 = __float2bfloat16(v.w);
    *(__nv_bfloat162*)(hi + (size_t)idx * 4)     = __halves2bfloat162(h0, h1);
    *(__nv_bfloat162*)(hi + (size_t)idx * 4 + 2) = __halves2bfloat162(h2, h3);
    *(__nv_bfloat162*)(lo + (size_t)idx * 4)     =
        __halves2bfloat162(__float2bfloat16(v.x - __bfloat162float(h0)),
                           __float2bfloat16(v.y - __bfloat162float(h1)));
    *(__nv_bfloat162*)(lo + (size_t)idx * 4 + 2) =
        __halves2bfloat162(__float2bfloat16(v.z - __bfloat162float(h2)),
                           __float2bfloat16(v.w - __bfloat162float(h3)));
}

__global__ void init_kernel(const float* __restrict__ b_lstm,
                            float* __restrict__ b4,
                            float* __restrict__ h0,
                            unsigned* __restrict__ bar,
                            unsigned* __restrict__ q,
                            unsigned* __restrict__ ready) {
    int idx = blockIdx.x * blockDim.x + threadIdx.x;
    if (idx == 0) { *bar = 0u; *q = 0u; }
    if (idx < T_) ready[idx] = 0u;
    if (idx < G4_) b4[idx] = b_lstm[(idx & 3) * U_ + (idx >> 2)];
    if (idx < B_ * U_) h0[idx] = 0.0f;
}

// ---------------------------------------------------------------------------
// Stand-alone tensor GEMM (frozen R7) for phase 3.
// ---------------------------------------------------------------------------
__global__ __launch_bounds__(256, 2) void tgemm2(
    const __nv_bfloat16* __restrict__ Ah, const __nv_bfloat16* __restrict__ Al,
    const __nv_bfloat16* __restrict__ Bh, const __nv_bfloat16* __restrict__ Bl,
    const float* __restrict__ bias, float* __restrict__ C,
    int M, int N, int K, int relu)
{
    extern __shared__ __nv_bfloat16 ts[];

    int tid  = threadIdx.x;
    int warp = tid >> 5, lane = tid & 31;
    int wm = warp >> 1, wn = warp & 1;
    int m0 = blockIdx.y * 128, n0 = blockIdx.x * 128;

    int a1r = tid >> 2,         a1s = tid & 3;
    int a2r = (tid + 256) >> 2, a2s = (tid + 256) & 3;
    int b1r = tid >> 4,         b1s = tid & 15;
    int b2r = (tid + 256) >> 4, b2s = (tid + 256) & 15;

    float acc[2][8][4];
    #pragma unroll
    for (int i = 0; i < 2; i++)
        #pragma unroll
        for (int j = 0; j < 8; j++)
            #pragma unroll
            for (int q = 0; q < 4; q++) acc[i][j][q] = 0.0f;

    int a_r = (lane & 15);
    int a_c = (lane >> 4) * 8;
    int aoffA = (wm * 32 + a_r) * APITCH + a_c;
    int aoffB = a_r * BPITCH + wn * 64 + a_c;

    int KT = K / BKT;

    auto load_stage = [&](int kt, int s) {
        __nv_bfloat16* st = ts + s * STAGE_ELEM;
        __nv_bfloat16* sAh = st;
        __nv_bfloat16* sAl = st + SA_ELEM;
        __nv_bfloat16* sBh = st + 2 * SA_ELEM;
        __nv_bfloat16* sBl = st + 2 * SA_ELEM + SB_ELEM;
        int k0 = kt * BKT;
        const __nv_bfloat16* gAh = Ah + (size_t)m0 * K + k0;
        const __nv_bfloat16* gAl = Al + (size_t)m0 * K + k0;
        const __nv_bfloat16* gBh = Bh + (size_t)k0 * N + n0;
        const __nv_bfloat16* gBl = Bl + (size_t)k0 * N + n0;
        cpa16(smem_u32(sAh + a1r * APITCH + a1s * 8), gAh + (size_t)a1r * K + a1s * 8);
        cpa16(smem_u32(sAh + a2r * APITCH + a2s * 8), gAh + (size_t)a2r * K + a2s * 8);
        cpa16(smem_u32(sAl + a1r * APITCH + a1s * 8), gAl + (size_t)a1r * K + a1s * 8);
        cpa16(smem_u32(sAl + a2r * APITCH + a2s * 8), gAl + (size_t)a2r * K + a2s * 8);
        cpa16(smem_u32(sBh + b1r * BPITCH + b1s * 8), gBh + (size_t)b1r * N + b1s * 8);
        cpa16(smem_u32(sBh + b2r * BPITCH + b2s * 8), gBh + (size_t)b2r * N + b2s * 8);
        cpa16(smem_u32(sBl + b1r * BPITCH + b1s * 8), gBl + (size_t)b1r * N + b1s * 8);
        cpa16(smem_u32(sBl + b2r * BPITCH + b2s * 8), gBl + (size_t)b2r * N + b2s * 8);
    };

    load_stage(0, 0);
    cpa_commit();
    cpa_wait0();
    __syncthreads();

    for (int kt = 0; kt < KT; kt++) {
        int cur = kt & 1;
        if (kt + 1 < KT) {
            load_stage(kt + 1, cur ^ 1);
            cpa_commit();
        }

        __nv_bfloat16* st = ts + cur * STAGE_ELEM;
        uint32_t aAh = smem_u32(st + aoffA);
        uint32_t aAl = smem_u32(st + SA_ELEM + aoffA);
        uint32_t aBh = smem_u32(st + 2 * SA_ELEM + aoffB);
        uint32_t aBl = smem_u32(st + 2 * SA_ELEM + SB_ELEM + aoffB);

        #pragma unroll
        for (int kk = 0; kk < 2; kk++) {
            uint32_t Ahf[2][4], Alf[2][4];
            #pragma unroll
            for (int mt = 0; mt < 2; mt++) {
                uint32_t off = (mt * 16) * APITCH * 2 + kk * 16 * 2;
                ldsm_x4(Ahf[mt][0], Ahf[mt][1], Ahf[mt][2], Ahf[mt][3], aAh + off);
                ldsm_x4(Alf[mt][0], Alf[mt][1], Alf[mt][2], Alf[mt][3], aAl + off);
            }
            uint32_t Bhf[8][2], Blf[8][2];
            #pragma unroll
            for (int p = 0; p < 4; p++) {
                uint32_t off = (kk * 16) * BPITCH * 2 + p * 16 * 2;
                ldsm_x4t(Bhf[2*p][0], Bhf[2*p][1], Bhf[2*p+1][0], Bhf[2*p+1][1], aBh + off);
                ldsm_x4t(Blf[2*p][0], Blf[2*p][1], Blf[2*p+1][0], Blf[2*p+1][1], aBl + off);
            }
            #pragma unroll
            for (int mt = 0; mt < 2; mt++)
                #pragma unroll
                for (int nt = 0; nt < 8; nt++) {
                    mma_bf16(acc[mt][nt], Ahf[mt], Bhf[nt]);
                    mma_bf16(acc[mt][nt], Ahf[mt], Blf[nt]);
                    mma_bf16(acc[mt][nt], Alf[mt], Bhf[nt]);
                }
        }

        if (kt + 1 < KT) cpa_wait0();
        __syncthreads();
    }

    int crow = lane >> 2;
    int ccol = (lane & 3) * 2;
    #pragma unroll
    for (int mt = 0; mt < 2; mt++) {
        int r0 = m0 + wm * 32 + mt * 16 + crow;
        #pragma unroll
        for (int nt = 0; nt < 8; nt++) {
            int cglob = n0 + wn * 64 + nt * 8 + ccol;
            float b0 = bias[cglob], b1 = bias[cglob + 1];
            float2 v0 = { acc[mt][nt][0] + b0, acc[mt][nt][1] + b1 };
            float2 v1 = { acc[mt][nt][2] + b0, acc[mt][nt][3] + b1 };
            if (relu) {
                v0.x = fmaxf(v0.x, 0.f); v0.y = fmaxf(v0.y, 0.f);
                v1.x = fmaxf(v1.x, 0.f); v1.y = fmaxf(v1.y, 0.f);
            }
            *(float2*)(C + (size_t)r0 * N + cglob)       = v0;
            *(float2*)(C + (size_t)(r0 + 8) * N + cglob) = v1;
        }
    }
}

// ---------------------------------------------------------------------------
// FUSED phase1+phase2: 128 blocks x 512 threads, 1 block/SM (64K-reg cap).
// Threads 0-255: R7 recurrence (bar.sync 1). Threads 256-511: phase-1 GEMM
// worker pulling t-major tiles from a global queue (bar.sync 2), publishing
// ready[t] after each tile. Recurrence waits ready[t]==16 before gates.
// ---------------------------------------------------------------------------
__global__ __launch_bounds__(512, 1) void fused_p12(
    const __nv_bfloat16* __restrict__ Ah, const __nv_bfloat16* __restrict__ Al,
    const __nv_bfloat16* __restrict__ Bh, const __nv_bfloat16* __restrict__ Bl,
    const float* __restrict__ b4, float* xz,
    const float* __restrict__ h0, const float* __restrict__ Wrec,
    float* hseq, unsigned* bar, unsigned* q, unsigned* ready)
{
    extern __shared__ char smemc[];
    int tid = threadIdx.x;

    if (tid < 256) {
        // ------------------ RECURRENCE ROLE (R7 scalar, bar 1) ------------
        float* Ws = (float*)(smemc + FS_WS);     // [512][16]
        float* Hs = (float*)(smemc + FS_HS);     // [KC][129]
        int rtid = tid;
        int blk = blockIdx.x;
        int n0 = blk * 16;
        int tx = rtid & 3;
        int ty = rtid >> 2;
        int u  = blk * 4 + tx;

        for (int l = rtid; l < 512 * 4; l += 256) {
            int row = l >> 2, c4 = l & 3;
            *(float4*)&Ws[row * 16 + c4 * 4] =
                *(const float4*)(Wrec + (size_t)row * G4_ + n0 + c4 * 4);
        }

        float creg0 = 0.0f, creg1 = 0.0f;
        const float* hp = h0;

        for (int t = 0; t < T_; t++) {
            float acc[2][4];
            #pragma unroll
            for (int i = 0; i < 2; i++)
                #pragma unroll
                for (int j = 0; j < 4; j++) acc[i][j] = 0.0f;

            for (int k0 = 0; k0 < U_; k0 += KC) {
                #pragma unroll
                for (int i = 0; i < 4; i++) {
                    int l = rtid + i * 256;
                    int b = l >> 3, k4 = l & 7;
                    float4 v = __ldcg((const float4*)(hp + (size_t)b * U_ + k0 + k4 * 4));
                    Hs[(k4 * 4 + 0) * 129 + b] = v.x;
                    Hs[(k4 * 4 + 1) * 129 + b] = v.y;
                    Hs[(k4 * 4 + 2) * 129 + b] = v.z;
                    Hs[(k4 * 4 + 3) * 129 + b] = v.w;
                }
                BARR1;

                #pragma unroll
                for (int kk = 0; kk < KC; kk++) {
                    float4 wv = *(float4*)&Ws[(k0 + kk) * 16 + tx * 4];
                    float ha = Hs[kk * 129 + ty * 2 + 0];
                    float hb = Hs[kk * 129 + ty * 2 + 1];
                    acc[0][0] += ha * wv.x; acc[0][1] += ha * wv.y;
                    acc[0][2] += ha * wv.z; acc[0][3] += ha * wv.w;
                    acc[1][0] += hb * wv.x; acc[1][1] += hb * wv.y;
                    acc[1][2] += hb * wv.z; acc[1][3] += hb * wv.w;
                }
                BARR1;
            }

            // wait for this timestep's xz tiles (produced by GEMM role)
            if (rtid == 0) {
                while (((volatile unsigned*)ready)[t] < 16u) {}
                __threadfence();
            }
            BARR1;

            #pragma unroll
            for (int i = 0; i < 2; i++) {
                int b = ty * 2 + i;
                const float4* xzp = (const float4*)(xz + ((size_t)t * B_ + b) * G4_ + n0 + tx * 4);
                float4 xv = __ldcg(xzp);
                float zi = acc[i][0] + xv.x;
                float zf = acc[i][1] + xv.y;
                float zg = acc[i][2] + xv.z;
                float zo = acc[i][3] + xv.w;
                float ig = 1.0f / (1.0f + expf(-zi));
                float fg = 1.0f / (1.0f + expf(-zf));
                float gg = tanhf(zg);
                float og = 1.0f / (1.0f + expf(-zo));
                float cp = i ? creg1 : creg0;
                float cn = fg * cp + ig * gg;
                if (i) creg1 = cn; else creg0 = cn;
                hseq[((size_t)t * B_ + b) * U_ + u] = og * tanhf(cn);
            }

            __threadfence();
            BARR1;
            if (rtid == 0) {
                atomicAdd(bar, 1u);
                unsigned target = (unsigned)RBLK * (unsigned)(t + 1);
                while (*(volatile unsigned*)bar < target) {}
            }
            BARR1;

            hp = hseq + (size_t)t * B_ * U_;
        }
    } else {
        // ------------------ GEMM ROLE (phase 1, bar 2, tile queue) --------
        __nv_bfloat16* ts = (__nv_bfloat16*)smemc;
        volatile int* sm_tile = (volatile int*)(smemc + FS_TILE);
        int wtid = tid - 256;
        int warp = wtid >> 5, lane = wtid & 31;
        int wm = warp >> 1, wn = warp & 1;

        int a1r = wtid >> 2,         a1s = wtid & 3;
        int a2r = (wtid + 256) >> 2, a2s = (wtid + 256) & 3;
        int b1r = wtid >> 4,         b1s = wtid & 15;
        int b2r = (wtid + 256) >> 4, b2s = (wtid + 256) & 15;

        int a_r = (lane & 15);
        int a_c = (lane >> 4) * 8;
        int aoffA = (wm * 32 + a_r) * APITCH + a_c;
        int aoffB = a_r * BPITCH + wn * 64 + a_c;

        const int Kg = F_, Ng = G4_, KT = F_ / BKT;

        for (;;) {
            if (wtid == 0) *sm_tile = (int)atomicAdd(q, 1u);
            BARR2;
            int tile = *sm_tile;
            BARR2;
            if (tile >= P1_TILES) break;
            int m0 = (tile >> 4) * 128;     // t-major: tile = t*16 + ncol
            int n0 = (tile & 15) * 128;

            float acc[2][8][4];
            #pragma unroll
            for (int i = 0; i < 2; i++)
                #pragma unroll
                for (int j = 0; j < 8; j++)
                    #pragma unroll
                    for (int qq = 0; qq < 4; qq++) acc[i][j][qq] = 0.0f;

            auto load_stage = [&](int kt, int s) {
                __nv_bfloat16* st = ts + s * STAGE_ELEM;
                __nv_bfloat16* sAh = st;
                __nv_bfloat16* sAl = st + SA_ELEM;
                __nv_bfloat16* sBh = st + 2 * SA_ELEM;
                __nv_bfloat16* sBl = st + 2 * SA_ELEM + SB_ELEM;
                int k0 = kt * BKT;
                const __nv_bfloat16* gAh = Ah + (size_t)m0 * Kg + k0;
                const __nv_bfloat16* gAl = Al + (size_t)m0 * Kg + k0;
                const __nv_bfloat16* gBh = Bh + (size_t)k0 * Ng + n0;
                const __nv_bfloat16* gBl = Bl + (size_t)k0 * Ng + n0;
                cpa16(smem_u32(sAh + a1r * APITCH + a1s * 8), gAh + (size_t)a1r * Kg + a1s * 8);
                cpa16(smem_u32(sAh + a2r * APITCH + a2s * 8), gAh + (size_t)a2r * Kg + a2s * 8);
                cpa16(smem_u32(sAl + a1r * APITCH + a1s * 8), gAl + (size_t)a1r * Kg + a1s * 8);
                cpa16(smem_u32(sAl + a2r * APITCH + a2s * 8), gAl + (size_t)a2r * Kg + a2s * 8);
                cpa16(smem_u32(sBh + b1r * BPITCH + b1s * 8), gBh + (size_t)b1r * Ng + b1s * 8);
                cpa16(smem_u32(sBh + b2r * BPITCH + b2s * 8), gBh + (size_t)b2r * Ng + b2s * 8);
                cpa16(smem_u32(sBl + b1r * BPITCH + b1s * 8), gBl + (size_t)b1r * Ng + b1s * 8);
                cpa16(smem_u32(sBl + b2r * BPITCH + b2s * 8), gBl + (size_t)b2r * Ng + b2s * 8);
            };

            load_stage(0, 0);
            cpa_commit();
            cpa_wait0();
            BARR2;

            for (int kt = 0; kt < KT; kt++) {
                int cur = kt & 1;
                if (kt + 1 < KT) {
                    load_stage(kt + 1, cur ^ 1);
                    cpa_commit();
                }

                __nv_bfloat16* st = ts + cur * STAGE_ELEM;
                uint32_t aAh = smem_u32(st + aoffA);
                uint32_t aAl = smem_u32(st + SA_ELEM + aoffA);
                uint32_t aBh = smem_u32(st + 2 * SA_ELEM + aoffB);
                uint32_t aBl = smem_u32(st + 2 * SA_ELEM + SB_ELEM + aoffB);

                #pragma unroll
                for (int kk = 0; kk < 2; kk++) {
                    uint32_t Ahf[2][4], Alf[2][4];
                    #pragma unroll
                    for (int mt = 0; mt < 2; mt++) {
                        uint32_t off = (mt * 16) * APITCH * 2 + kk * 16 * 2;
                        ldsm_x4(Ahf[mt][0], Ahf[mt][1], Ahf[mt][2], Ahf[mt][3], aAh + off);
                        ldsm_x4(Alf[mt][0], Alf[mt][1], Alf[mt][2], Alf[mt][3], aAl + off);
                    }
                    uint32_t Bhf[8][2], Blf[8][2];
                    #pragma unroll
                    for (int p = 0; p < 4; p++) {
                        uint32_t off = (kk * 16) * BPITCH * 2 + p * 16 * 2;
                        ldsm_x4t(Bhf[2*p][0], Bhf[2*p][1], Bhf[2*p+1][0], Bhf[2*p+1][1], aBh + off);
                        ldsm_x4t(Blf[2*p][0], Blf[2*p][1], Blf[2*p+1][0], Blf[2*p+1][1], aBl + off);
                    }
                    #pragma unroll
                    for (int mt = 0; mt < 2; mt++)
                        #pragma unroll
                        for (int nt = 0; nt < 8; nt++) {
                            mma_bf16(acc[mt][nt], Ahf[mt], Bhf[nt]);
                            mma_bf16(acc[mt][nt], Ahf[mt], Blf[nt]);
                            mma_bf16(acc[mt][nt], Alf[mt], Bhf[nt]);
                        }
                }

                if (kt + 1 < KT) cpa_wait0();
                BARR2;
            }

            int crow = lane >> 2;
            int ccol = (lane & 3) * 2;
            #pragma unroll
            for (int mt = 0; mt < 2; mt++) {
                int r0 = m0 + wm * 32 + mt * 16 + crow;
                #pragma unroll
                for (int nt = 0; nt < 8; nt++) {
                    int cglob = n0 + wn * 64 + nt * 8 + ccol;
                    float b0 = b4[cglob], b1 = b4[cglob + 1];
                    float2 v0 = { acc[mt][nt][0] + b0, acc[mt][nt][1] + b1 };
                    float2 v1 = { acc[mt][nt][2] + b0, acc[mt][nt][3] + b1 };
                    *(float2*)(xz + (size_t)r0 * Ng + cglob)       = v0;
                    *(float2*)(xz + (size_t)(r0 + 8) * Ng + cglob) = v1;
                }
            }

            __threadfence();
            BARR2;
            if (wtid == 0) atomicAdd(ready + (m0 >> 7), 1u);
        }
    }
}

// ---------------------------------------------------------------------------
// In-place row softmax (1024 cols, one block/row).
// ---------------------------------------------------------------------------
__global__ __launch_bounds__(256) void softmax_kernel(float* __restrict__ out) {
    __shared__ float red[8];
    int tid = threadIdx.x;
    float* p = out + (size_t)blockIdx.x * CODES_;

    float4 v = *(float4*)(p + tid * 4);
    float m = fmaxf(fmaxf(v.x, v.y), fmaxf(v.z, v.w));
    #pragma unroll
    for (int o = 16; o > 0; o >>= 1) m = fmaxf(m, __shfl_xor_sync(0xFFFFFFFFu, m, o));
    if ((tid & 31) == 0) red[tid >> 5] = m;
    __syncthreads();
    float bm = red[0];
    #pragma unroll
    for (int i = 1; i < 8; i++) bm = fmaxf(bm, red[i]);
    __syncthreads();

    v.x = expf(v.x - bm); v.y = expf(v.y - bm);
    v.z = expf(v.z - bm); v.w = expf(v.w - bm);
    float s = v.x + v.y + v.z + v.w;
    #pragma unroll
    for (int o = 16; o > 0; o >>= 1) s += __shfl_xor_sync(0xFFFFFFFFu, s, o);
    if ((tid & 31) == 0) red[tid >> 5] = s;
    __syncthreads();
    float bs = red[0];
    #pragma unroll
    for (int i = 1; i < 8; i++) bs += red[i];
    float inv = 1.0f / bs;
    v.x *= inv; v.y *= inv; v.z *= inv; v.w *= inv;
    *(float4*)(p + tid * 4) = v;
}

// ---------------------------------------------------------------------------
// Launch
// ---------------------------------------------------------------------------
extern "C" void kernel_launch(void* const* d_in, const int* in_sizes, int n_in,
                              void* d_out, int out_size) {
    const float* x       = (const float*)d_in[0];
    const float* mask    = (const float*)d_in[1];
    const float* W_in    = (const float*)d_in[2];
    const float* W_rec   = (const float*)d_in[3];
    const float* b_lstm  = (const float*)d_in[4];
    const float* W_dense = (const float*)d_in[5];
    const float* b_dense = (const float*)d_in[6];
    float* out = (float*)d_out;

    float *xz, *hseq, *h0, *Wrec4, *b4;
    unsigned *bar, *q, *ready;
    __nv_bfloat16 *xh, *xl, *Wih, *Wil, *Wdh, *Wdl, *hh, *hl;
    cudaGetSymbolAddress((void**)&xz,    g_xz);
    cudaGetSymbolAddress((void**)&hseq,  g_hseq);
    cudaGetSymbolAddress((void**)&h0,    g_h0);
    cudaGetSymbolAddress((void**)&Wrec4, g_Wrec4);
    cudaGetSymbolAddress((void**)&b4,    g_b4);
    cudaGetSymbolAddress((void**)&bar,   g_bar);
    cudaGetSymbolAddress((void**)&q,     g_q);
    cudaGetSymbolAddress((void**)&ready, g_ready);
    cudaGetSymbolAddress((void**)&xh,    g_xh);
    cudaGetSymbolAddress((void**)&xl,    g_xl);
    cudaGetSymbolAddress((void**)&Wih,   g_Wih);
    cudaGetSymbolAddress((void**)&Wil,   g_Wil);
    cudaGetSymbolAddress((void**)&Wdh,   g_Wdh);
    cudaGetSymbolAddress((void**)&Wdl,   g_Wdl);
    cudaGetSymbolAddress((void**)&hh,    g_hh);
    cudaGetSymbolAddress((void**)&hl,    g_hl);

    cudaFuncSetAttribute(fused_p12,
                         cudaFuncAttributeMaxDynamicSharedMemorySize, FUSED_SMEM);
    cudaFuncSetAttribute(tgemm2,
                         cudaFuncAttributeMaxDynamicSharedMemorySize, GEMM_SMEM);

    // Pre-passes
    reorder_gates<<<(U_ * G4_ + 255) / 256, 256>>>(W_rec, Wrec4, U_ * G4_);
    reorder_split<<<(F_ * G4_ + 255) / 256, 256>>>(W_in, Wih, Wil, F_ * G4_);
    convert_split<<<(U_ * CODES_ / 4 + 255) / 256, 256>>>(W_dense, Wdh, Wdl, U_ * CODES_ / 4);
    convert_split<<<((int)((size_t)ROWS_ * F_ / 4) + 255) / 256, 256>>>(x, xh, xl, (int)((size_t)ROWS_ * F_ / 4));
    init_kernel<<<(B_ * U_ + 255) / 256, 256>>>(b_lstm, b4, h0, bar, q, ready);

    // Phase 1+2 fused: xz GEMM producer + LSTM recurrence consumer
    fused_p12<<<RBLK, 512, FUSED_SMEM>>>(
        xh, xl, Wih, Wil, b4, xz, h0, Wrec4, hseq, bar, q, ready);

    // Phase 2.5: masked h -> bf16 hi/lo
    convert_mask<<<((int)((size_t)ROWS_ * U_ / 4) + 255) / 256, 256>>>(
        hseq, mask, hh, hl, (int)((size_t)ROWS_ * U_ / 4));

    // Phase 3: logits = relu(masked_h @ W_dense + b_dense)
    tgemm2<<<dim3(CODES_ / 128, ROWS_ / 128), 256, GEMM_SMEM>>>(
        hh, hl, Wdh, Wdl, b_dense, out, ROWS_, CODES_, U_, 1);

    // Phase 4: softmax
    softmax_kernel<<<ROWS_, 256>>>(out);
}

// round 10
// speedup vs baseline: 1.3233x; 1.0201x over previous
#include <cuda_runtime.h>
#include <cuda_bf16.h>
#include <math.h>
#include <stdint.h>

// Problem constants
#define T_   256
#define B_   128
#define F_   1024
#define U_   512
#define G4_  2048   // 4*U
#define CODES_ 1024
#define ROWS_ 32768 // T*B

#define RBLK 128    // fused persistent blocks (1/SM)
#define KC   32     // recurrence K chunk

// Tensor GEMM tile: 128x128, K-chunk 64
#define BKT  64
#define APITCH 72   // 64 + 8 pad (bf16): 144B rows ≡16 mod 128 -> conflict-free
#define BPITCH 136  // 128 + 8 pad: 272B rows ≡16 mod 128
#define SA_ELEM (128 * APITCH)                  // 9216
#define SB_ELEM (BKT * BPITCH)                  // 8704
#define STAGE_ELEM (2 * SA_ELEM + 2 * SB_ELEM)  // 35840
#define GEMM_SMEM (2 * STAGE_ELEM * 2)          // 143360 B

// Fused kernel smem layout (bytes)
#define FS_WS   GEMM_SMEM                        // 143360: W_rec slice (512x16 f32)
#define FS_HS   (FS_WS + 512 * 16 * 4)           // 176128: Hs (KC x 129 f32)
#define FS_TILE (FS_HS + KC * 129 * 4)           // 192640: tile broadcast slot
#define FUSED_SMEM (FS_TILE + 16)                // 192656

#define P1_TILES (T_ * (G4_ / 128))              // 4096 tiles, 16 per timestep

#define BARR1 asm volatile("bar.sync 1, 256;" ::: "memory")
#define BARR2 asm volatile("bar.sync 2, 256;" ::: "memory")

// ---------------------------------------------------------------------------
// Scratch
// ---------------------------------------------------------------------------
__device__ float g_xz   [(size_t)ROWS_ * G4_];
__device__ float g_hseq [(size_t)ROWS_ * U_];
__device__ float g_h0   [B_ * U_];
__device__ float g_Wrec4[(size_t)U_ * G4_];
__device__ float g_b4   [G4_];
__device__ unsigned g_bar;
__device__ unsigned g_q;
__device__ unsigned g_ready[T_];

__device__ __nv_bfloat16 g_xh [(size_t)ROWS_ * F_];
__device__ __nv_bfloat16 g_xl [(size_t)ROWS_ * F_];
__device__ __nv_bfloat16 g_Wih[(size_t)F_ * G4_];
__device__ __nv_bfloat16 g_Wil[(size_t)F_ * G4_];
__device__ __nv_bfloat16 g_Wdh[(size_t)U_ * CODES_];
__device__ __nv_bfloat16 g_Wdl[(size_t)U_ * CODES_];
__device__ __nv_bfloat16 g_hh [(size_t)ROWS_ * U_];
__device__ __nv_bfloat16 g_hl [(size_t)ROWS_ * U_];

// ---------------------------------------------------------------------------
// Helpers
// ---------------------------------------------------------------------------
__device__ __forceinline__ uint32_t smem_u32(const void* p) {
    return (uint32_t)__cvta_generic_to_shared(p);
}
__device__ __forceinline__ void cpa16(uint32_t dst, const void* src) {
    asm volatile("cp.async.cg.shared.global [%0], [%1], 16;\n" :: "r"(dst), "l"(src));
}
__device__ __forceinline__ void cpa_commit() { asm volatile("cp.async.commit_group;\n" ::); }
__device__ __forceinline__ void cpa_wait0()  { asm volatile("cp.async.wait_group 0;\n" ::); }
__device__ __forceinline__ void ldsm_x4(uint32_t& r0, uint32_t& r1, uint32_t& r2, uint32_t& r3, uint32_t a) {
    asm volatile("ldmatrix.sync.aligned.m8n8.x4.shared.b16 {%0,%1,%2,%3},[%4];"
                 : "=r"(r0), "=r"(r1), "=r"(r2), "=r"(r3) : "r"(a));
}
__device__ __forceinline__ void ldsm_x4t(uint32_t& r0, uint32_t& r1, uint32_t& r2, uint32_t& r3, uint32_t a) {
    asm volatile("ldmatrix.sync.aligned.m8n8.x4.trans.shared.b16 {%0,%1,%2,%3},[%4];"
                 : "=r"(r0), "=r"(r1), "=r"(r2), "=r"(r3) : "r"(a));
}
__device__ __forceinline__ void mma_bf16(float c[4], const uint32_t a[4], const uint32_t b[2]) {
    asm volatile(
        "mma.sync.aligned.m16n8k16.row.col.f32.bf16.bf16.f32 "
        "{%0,%1,%2,%3},{%4,%5,%6,%7},{%8,%9},{%0,%1,%2,%3};"
        : "+f"(c[0]), "+f"(c[1]), "+f"(c[2]), "+f"(c[3])
        : "r"(a[0]), "r"(a[1]), "r"(a[2]), "r"(a[3]), "r"(b[0]), "r"(b[1]));
}

// ---------------------------------------------------------------------------
// Pre-pass kernels
// ---------------------------------------------------------------------------
__global__ void reorder_gates(const float* __restrict__ W, float* __restrict__ W4, int total) {
    int idx = blockIdx.x * blockDim.x + threadIdx.x;
    if (idx >= total) return;
    int col = idx & (G4_ - 1);
    int k   = idx >> 11;
    W4[idx] = W[(size_t)k * G4_ + (col & 3) * U_ + (col >> 2)];
}

__global__ void reorder_split(const float* __restrict__ W,
                              __nv_bfloat16* __restrict__ hi,
                              __nv_bfloat16* __restrict__ lo, int total) {
    int idx = blockIdx.x * blockDim.x + threadIdx.x;
    if (idx >= total) return;
    int col = idx & (G4_ - 1);
    int k   = idx >> 11;
    float v = W[(size_t)k * G4_ + (col & 3) * U_ + (col >> 2)];
    __nv_bfloat16 h = __float2bfloat16(v);
    hi[idx] = h;
    lo[idx] = __float2bfloat16(v - __bfloat162float(h));
}

__global__ void convert_split(const float* __restrict__ src,
                              __nv_bfloat16* __restrict__ hi,
                              __nv_bfloat16* __restrict__ lo, int n4) {
    int idx = blockIdx.x * blockDim.x + threadIdx.x;
    if (idx >= n4) return;
    float4 v = *(const float4*)(src + (size_t)idx * 4);
    __nv_bfloat16 h0 = __float2bfloat16(v.x), h1 = __float2bfloat16(v.y);
    __nv_bfloat16 h2 = __float2bfloat16(v.z), h3 = __float2bfloat16(v.w);
    *(__nv_bfloat162*)(hi + (size_t)idx * 4)     = __halves2bfloat162(h0, h1);
    *(__nv_bfloat162*)(hi + (size_t)idx * 4 + 2) = __halves2bfloat162(h2, h3);
    *(__nv_bfloat162*)(lo + (size_t)idx * 4)     =
        __halves2bfloat162(__float2bfloat16(v.x - __bfloat162float(h0)),
                           __float2bfloat16(v.y - __bfloat162float(h1)));
    *(__nv_bfloat162*)(lo + (size_t)idx * 4 + 2) =
        __halves2bfloat162(__float2bfloat16(v.z - __bfloat162float(h2)),
                           __float2bfloat16(v.w - __bfloat162float(h3)));
}

__global__ void convert_mask(const float* __restrict__ hseq,
                             const float* __restrict__ mask,
                             __nv_bfloat16* __restrict__ hi,
                             __nv_bfloat16* __restrict__ lo, int n4) {
    int idx = blockIdx.x * blockDim.x + threadIdx.x;
    if (idx >= n4) return;
    float m = mask[(idx * 4) >> 9];
    float4 v = *(const float4*)(hseq + (size_t)idx * 4);
    v.x *= m; v.y *= m; v.z *= m; v.w *= m;
    __nv_bfloat16 h0 = __float2bfloat16(v.x), h1 = __float2bfloat16(v.y);
    __nv_bfloat16 h2 = __float2bfloat16(v.z), h3 = __float2bfloat16(v.w);
    *(__nv_bfloat162*)(hi + (size_t)idx * 4)     = __halves2bfloat162(h0, h1);
    *(__nv_bfloat162*)(hi + (size_t)idx * 4 + 2) = __halves2bfloat162(h2, h3);
    *(__nv_bfloat162*)(lo + (size_t)idx * 4)     =
        __halves2bfloat162(__float2bfloat16(v.x - __bfloat162float(h0)),
                           __float2bfloat16(v.y - __bfloat162float(h1)));
    *(__nv_bfloat162*)(lo + (size_t)idx * 4 + 2) =
        __halves2bfloat162(__float2bfloat16(v.z - __bfloat162float(h2)),
                           __float2bfloat16(v.w - __bfloat162float(h3)));
}

__global__ void init_kernel(const float* __restrict__ b_lstm,
                            float* __restrict__ b4,
                            float* __restrict__ h0,
                            unsigned* __restrict__ bar,
                            unsigned* __restrict__ q,
                            unsigned* __restrict__ ready) {
    int idx = blockIdx.x * blockDim.x + threadIdx.x;
    if (idx == 0) { *bar = 0u; *q = 0u; }
    if (idx < T_) ready[idx] = 0u;
    if (idx < G4_) b4[idx] = b_lstm[(idx & 3) * U_ + (idx >> 2)];
    if (idx < B_ * U_) h0[idx] = 0.0f;
}

// ---------------------------------------------------------------------------
// Stand-alone tensor GEMM (BKT=64) for phase 3.
// ---------------------------------------------------------------------------
__global__ __launch_bounds__(256, 1) void tgemm2(
    const __nv_bfloat16* __restrict__ Ah, const __nv_bfloat16* __restrict__ Al,
    const __nv_bfloat16* __restrict__ Bh, const __nv_bfloat16* __restrict__ Bl,
    const float* __restrict__ bias, float* __restrict__ C,
    int M, int N, int K, int relu)
{
    extern __shared__ __nv_bfloat16 ts[];

    int tid  = threadIdx.x;
    int warp = tid >> 5, lane = tid & 31;
    int wm = warp >> 1, wn = warp & 1;
    int m0 = blockIdx.y * 128, n0 = blockIdx.x * 128;

    float acc[2][8][4];
    #pragma unroll
    for (int i = 0; i < 2; i++)
        #pragma unroll
        for (int j = 0; j < 8; j++)
            #pragma unroll
            for (int q = 0; q < 4; q++) acc[i][j][q] = 0.0f;

    int a_r = (lane & 15);
    int a_c = (lane >> 4) * 8;
    int aoffA = (wm * 32 + a_r) * APITCH + a_c;
    int aoffB = a_r * BPITCH + wn * 64 + a_c;

    int KT = K / BKT;

    auto load_stage = [&](int kt, int s) {
        __nv_bfloat16* st = ts + s * STAGE_ELEM;
        __nv_bfloat16* sAh = st;
        __nv_bfloat16* sAl = st + SA_ELEM;
        __nv_bfloat16* sBh = st + 2 * SA_ELEM;
        __nv_bfloat16* sBl = st + 2 * SA_ELEM + SB_ELEM;
        int k0 = kt * BKT;
        const __nv_bfloat16* gAh = Ah + (size_t)m0 * K + k0;
        const __nv_bfloat16* gAl = Al + (size_t)m0 * K + k0;
        const __nv_bfloat16* gBh = Bh + (size_t)k0 * N + n0;
        const __nv_bfloat16* gBl = Bl + (size_t)k0 * N + n0;
        #pragma unroll
        for (int j = 0; j < 4; j++) {
            int ca = tid + j * 256;                 // A: 128 rows x 8 segs
            int ar = ca >> 3, as = ca & 7;
            cpa16(smem_u32(sAh + ar * APITCH + as * 8), gAh + (size_t)ar * K + as * 8);
            cpa16(smem_u32(sAl + ar * APITCH + as * 8), gAl + (size_t)ar * K + as * 8);
            int cb = tid + j * 256;                 // B: 64 rows x 16 segs
            int br = cb >> 4, bs = cb & 15;
            cpa16(smem_u32(sBh + br * BPITCH + bs * 8), gBh + (size_t)br * N + bs * 8);
            cpa16(smem_u32(sBl + br * BPITCH + bs * 8), gBl + (size_t)br * N + bs * 8);
        }
    };

    load_stage(0, 0);
    cpa_commit();
    cpa_wait0();
    __syncthreads();

    for (int kt = 0; kt < KT; kt++) {
        int cur = kt & 1;
        if (kt + 1 < KT) {
            load_stage(kt + 1, cur ^ 1);
            cpa_commit();
        }

        __nv_bfloat16* st = ts + cur * STAGE_ELEM;
        uint32_t aAh = smem_u32(st + aoffA);
        uint32_t aAl = smem_u32(st + SA_ELEM + aoffA);
        uint32_t aBh = smem_u32(st + 2 * SA_ELEM + aoffB);
        uint32_t aBl = smem_u32(st + 2 * SA_ELEM + SB_ELEM + aoffB);

        #pragma unroll
        for (int kk = 0; kk < 4; kk++) {
            uint32_t Ahf[2][4], Alf[2][4];
            #pragma unroll
            for (int mt = 0; mt < 2; mt++) {
                uint32_t off = (mt * 16) * APITCH * 2 + kk * 16 * 2;
                ldsm_x4(Ahf[mt][0], Ahf[mt][1], Ahf[mt][2], Ahf[mt][3], aAh + off);
                ldsm_x4(Alf[mt][0], Alf[mt][1], Alf[mt][2], Alf[mt][3], aAl + off);
            }
            uint32_t Bhf[8][2], Blf[8][2];
            #pragma unroll
            for (int p = 0; p < 4; p++) {
                uint32_t off = (kk * 16) * BPITCH * 2 + p * 16 * 2;
                ldsm_x4t(Bhf[2*p][0], Bhf[2*p][1], Bhf[2*p+1][0], Bhf[2*p+1][1], aBh + off);
                ldsm_x4t(Blf[2*p][0], Blf[2*p][1], Blf[2*p+1][0], Blf[2*p+1][1], aBl + off);
            }
            #pragma unroll
            for (int mt = 0; mt < 2; mt++)
                #pragma unroll
                for (int nt = 0; nt < 8; nt++) {
                    mma_bf16(acc[mt][nt], Ahf[mt], Bhf[nt]);
                    mma_bf16(acc[mt][nt], Ahf[mt], Blf[nt]);
                    mma_bf16(acc[mt][nt], Alf[mt], Bhf[nt]);
                }
        }

        if (kt + 1 < KT) cpa_wait0();
        __syncthreads();
    }

    int crow = lane >> 2;
    int ccol = (lane & 3) * 2;
    #pragma unroll
    for (int mt = 0; mt < 2; mt++) {
        int r0 = m0 + wm * 32 + mt * 16 + crow;
        #pragma unroll
        for (int nt = 0; nt < 8; nt++) {
            int cglob = n0 + wn * 64 + nt * 8 + ccol;
            float b0 = bias[cglob], b1 = bias[cglob + 1];
            float2 v0 = { acc[mt][nt][0] + b0, acc[mt][nt][1] + b1 };
            float2 v1 = { acc[mt][nt][2] + b0, acc[mt][nt][3] + b1 };
            if (relu) {
                v0.x = fmaxf(v0.x, 0.f); v0.y = fmaxf(v0.y, 0.f);
                v1.x = fmaxf(v1.x, 0.f); v1.y = fmaxf(v1.y, 0.f);
            }
            *(float2*)(C + (size_t)r0 * N + cglob)       = v0;
            *(float2*)(C + (size_t)(r0 + 8) * N + cglob) = v1;
        }
    }
}

// ---------------------------------------------------------------------------
// FUSED phase1+phase2 (recurrence identical to R9; GEMM role BKT=64).
// ---------------------------------------------------------------------------
__global__ __launch_bounds__(512, 1) void fused_p12(
    const __nv_bfloat16* __restrict__ Ah, const __nv_bfloat16* __restrict__ Al,
    const __nv_bfloat16* __restrict__ Bh, const __nv_bfloat16* __restrict__ Bl,
    const float* __restrict__ b4, float* xz,
    const float* __restrict__ h0, const float* __restrict__ Wrec,
    float* hseq, unsigned* bar, unsigned* q, unsigned* ready)
{
    extern __shared__ char smemc[];
    int tid = threadIdx.x;

    if (tid < 256) {
        // ------------------ RECURRENCE ROLE (R7 scalar, bar 1) ------------
        float* Ws = (float*)(smemc + FS_WS);     // [512][16]
        float* Hs = (float*)(smemc + FS_HS);     // [KC][129]
        int rtid = tid;
        int blk = blockIdx.x;
        int n0 = blk * 16;
        int tx = rtid & 3;
        int ty = rtid >> 2;
        int u  = blk * 4 + tx;

        for (int l = rtid; l < 512 * 4; l += 256) {
            int row = l >> 2, c4 = l & 3;
            *(float4*)&Ws[row * 16 + c4 * 4] =
                *(const float4*)(Wrec + (size_t)row * G4_ + n0 + c4 * 4);
        }

        float creg0 = 0.0f, creg1 = 0.0f;
        const float* hp = h0;

        for (int t = 0; t < T_; t++) {
            float acc[2][4];
            #pragma unroll
            for (int i = 0; i < 2; i++)
                #pragma unroll
                for (int j = 0; j < 4; j++) acc[i][j] = 0.0f;

            for (int k0 = 0; k0 < U_; k0 += KC) {
                #pragma unroll
                for (int i = 0; i < 4; i++) {
                    int l = rtid + i * 256;
                    int b = l >> 3, k4 = l & 7;
                    float4 v = __ldcg((const float4*)(hp + (size_t)b * U_ + k0 + k4 * 4));
                    Hs[(k4 * 4 + 0) * 129 + b] = v.x;
                    Hs[(k4 * 4 + 1) * 129 + b] = v.y;
                    Hs[(k4 * 4 + 2) * 129 + b] = v.z;
                    Hs[(k4 * 4 + 3) * 129 + b] = v.w;
                }
                BARR1;

                #pragma unroll
                for (int kk = 0; kk < KC; kk++) {
                    float4 wv = *(float4*)&Ws[(k0 + kk) * 16 + tx * 4];
                    float ha = Hs[kk * 129 + ty * 2 + 0];
                    float hb = Hs[kk * 129 + ty * 2 + 1];
                    acc[0][0] += ha * wv.x; acc[0][1] += ha * wv.y;
                    acc[0][2] += ha * wv.z; acc[0][3] += ha * wv.w;
                    acc[1][0] += hb * wv.x; acc[1][1] += hb * wv.y;
                    acc[1][2] += hb * wv.z; acc[1][3] += hb * wv.w;
                }
                BARR1;
            }

            if (rtid == 0) {
                while (((volatile unsigned*)ready)[t] < 16u) {}
                __threadfence();
            }
            BARR1;

            #pragma unroll
            for (int i = 0; i < 2; i++) {
                int b = ty * 2 + i;
                const float4* xzp = (const float4*)(xz + ((size_t)t * B_ + b) * G4_ + n0 + tx * 4);
                float4 xv = __ldcg(xzp);
                float zi = acc[i][0] + xv.x;
                float zf = acc[i][1] + xv.y;
                float zg = acc[i][2] + xv.z;
                float zo = acc[i][3] + xv.w;
                float ig = 1.0f / (1.0f + expf(-zi));
                float fg = 1.0f / (1.0f + expf(-zf));
                float gg = tanhf(zg);
                float og = 1.0f / (1.0f + expf(-zo));
                float cp = i ? creg1 : creg0;
                float cn = fg * cp + ig * gg;
                if (i) creg1 = cn; else creg0 = cn;
                hseq[((size_t)t * B_ + b) * U_ + u] = og * tanhf(cn);
            }

            __threadfence();
            BARR1;
            if (rtid == 0) {
                atomicAdd(bar, 1u);
                unsigned target = (unsigned)RBLK * (unsigned)(t + 1);
                while (*(volatile unsigned*)bar < target) {}
            }
            BARR1;

            hp = hseq + (size_t)t * B_ * U_;
        }
    } else {
        // ------------------ GEMM ROLE (phase 1, BKT=64, bar 2) ------------
        __nv_bfloat16* ts = (__nv_bfloat16*)smemc;
        volatile int* sm_tile = (volatile int*)(smemc + FS_TILE);
        int wtid = tid - 256;
        int warp = wtid >> 5, lane = wtid & 31;
        int wm = warp >> 1, wn = warp & 1;

        int a_r = (lane & 15);
        int a_c = (lane >> 4) * 8;
        int aoffA = (wm * 32 + a_r) * APITCH + a_c;
        int aoffB = a_r * BPITCH + wn * 64 + a_c;

        const int Kg = F_, Ng = G4_, KT = F_ / BKT;

        for (;;) {
            if (wtid == 0) *sm_tile = (int)atomicAdd(q, 1u);
            BARR2;
            int tile = *sm_tile;
            BARR2;
            if (tile >= P1_TILES) break;
            int m0 = (tile >> 4) * 128;     // t-major: tile = t*16 + ncol
            int n0 = (tile & 15) * 128;

            float acc[2][8][4];
            #pragma unroll
            for (int i = 0; i < 2; i++)
                #pragma unroll
                for (int j = 0; j < 8; j++)
                    #pragma unroll
                    for (int qq = 0; qq < 4; qq++) acc[i][j][qq] = 0.0f;

            auto load_stage = [&](int kt, int s) {
                __nv_bfloat16* st = ts + s * STAGE_ELEM;
                __nv_bfloat16* sAh = st;
                __nv_bfloat16* sAl = st + SA_ELEM;
                __nv_bfloat16* sBh = st + 2 * SA_ELEM;
                __nv_bfloat16* sBl = st + 2 * SA_ELEM + SB_ELEM;
                int k0 = kt * BKT;
                const __nv_bfloat16* gAh = Ah + (size_t)m0 * Kg + k0;
                const __nv_bfloat16* gAl = Al + (size_t)m0 * Kg + k0;
                const __nv_bfloat16* gBh = Bh + (size_t)k0 * Ng + n0;
                const __nv_bfloat16* gBl = Bl + (size_t)k0 * Ng + n0;
                #pragma unroll
                for (int j = 0; j < 4; j++) {
                    int ca = wtid + j * 256;
                    int ar = ca >> 3, as = ca & 7;
                    cpa16(smem_u32(sAh + ar * APITCH + as * 8), gAh + (size_t)ar * Kg + as * 8);
                    cpa16(smem_u32(sAl + ar * APITCH + as * 8), gAl + (size_t)ar * Kg + as * 8);
                    int cb = wtid + j * 256;
                    int br = cb >> 4, bs = cb & 15;
                    cpa16(smem_u32(sBh + br * BPITCH + bs * 8), gBh + (size_t)br * Ng + bs * 8);
                    cpa16(smem_u32(sBl + br * BPITCH + bs * 8), gBl + (size_t)br * Ng + bs * 8);
                }
            };

            load_stage(0, 0);
            cpa_commit();
            cpa_wait0();
            BARR2;

            for (int kt = 0; kt < KT; kt++) {
                int cur = kt & 1;
                if (kt + 1 < KT) {
                    load_stage(kt + 1, cur ^ 1);
                    cpa_commit();
                }

                __nv_bfloat16* st = ts + cur * STAGE_ELEM;
                uint32_t aAh = smem_u32(st + aoffA);
                uint32_t aAl = smem_u32(st + SA_ELEM + aoffA);
                uint32_t aBh = smem_u32(st + 2 * SA_ELEM + aoffB);
                uint32_t aBl = smem_u32(st + 2 * SA_ELEM + SB_ELEM + aoffB);

                #pragma unroll
                for (int kk = 0; kk < 4; kk++) {
                    uint32_t Ahf[2][4], Alf[2][4];
                    #pragma unroll
                    for (int mt = 0; mt < 2; mt++) {
                        uint32_t off = (mt * 16) * APITCH * 2 + kk * 16 * 2;
                        ldsm_x4(Ahf[mt][0], Ahf[mt][1], Ahf[mt][2], Ahf[mt][3], aAh + off);
                        ldsm_x4(Alf[mt][0], Alf[mt][1], Alf[mt][2], Alf[mt][3], aAl + off);
                    }
                    uint32_t Bhf[8][2], Blf[8][2];
                    #pragma unroll
                    for (int p = 0; p < 4; p++) {
                        uint32_t off = (kk * 16) * BPITCH * 2 + p * 16 * 2;
                        ldsm_x4t(Bhf[2*p][0], Bhf[2*p][1], Bhf[2*p+1][0], Bhf[2*p+1][1], aBh + off);
                        ldsm_x4t(Blf[2*p][0], Blf[2*p][1], Blf[2*p+1][0], Blf[2*p+1][1], aBl + off);
                    }
                    #pragma unroll
                    for (int mt = 0; mt < 2; mt++)
                        #pragma unroll
                        for (int nt = 0; nt < 8; nt++) {
                            mma_bf16(acc[mt][nt], Ahf[mt], Bhf[nt]);
                            mma_bf16(acc[mt][nt], Ahf[mt], Blf[nt]);
                            mma_bf16(acc[mt][nt], Alf[mt], Bhf[nt]);
                        }
                }

                if (kt + 1 < KT) cpa_wait0();
                BARR2;
            }

            int crow = lane >> 2;
            int ccol = (lane & 3) * 2;
            #pragma unroll
            for (int mt = 0; mt < 2; mt++) {
                int r0 = m0 + wm * 32 + mt * 16 + crow;
                #pragma unroll
                for (int nt = 0; nt < 8; nt++) {
                    int cglob = n0 + wn * 64 + nt * 8 + ccol;
                    float b0 = b4[cglob], b1 = b4[cglob + 1];
                    float2 v0 = { acc[mt][nt][0] + b0, acc[mt][nt][1] + b1 };
                    float2 v1 = { acc[mt][nt][2] + b0, acc[mt][nt][3] + b1 };
                    *(float2*)(xz + (size_t)r0 * Ng + cglob)       = v0;
                    *(float2*)(xz + (size_t)(r0 + 8) * Ng + cglob) = v1;
                }
            }

            __threadfence();
            BARR2;
            if (wtid == 0) atomicAdd(ready + (m0 >> 7), 1u);
        }
    }
}

// ---------------------------------------------------------------------------
// In-place row softmax (1024 cols, one block/row).
// ---------------------------------------------------------------------------
__global__ __launch_bounds__(256) void softmax_kernel(float* __restrict__ out) {
    __shared__ float red[8];
    int tid = threadIdx.x;
    float* p = out + (size_t)blockIdx.x * CODES_;

    float4 v = *(float4*)(p + tid * 4);
    float m = fmaxf(fmaxf(v.x, v.y), fmaxf(v.z, v.w));
    #pragma unroll
    for (int o = 16; o > 0; o >>= 1) m = fmaxf(m, __shfl_xor_sync(0xFFFFFFFFu, m, o));
    if ((tid & 31) == 0) red[tid >> 5] = m;
    __syncthreads();
    float bm = red[0];
    #pragma unroll
    for (int i = 1; i < 8; i++) bm = fmaxf(bm, red[i]);
    __syncthreads();

    v.x = expf(v.x - bm); v.y = expf(v.y - bm);
    v.z = expf(v.z - bm); v.w = expf(v.w - bm);
    float s = v.x + v.y + v.z + v.w;
    #pragma unroll
    for (int o = 16; o > 0; o >>= 1) s += __shfl_xor_sync(0xFFFFFFFFu, s, o);
    if ((tid & 31) == 0) red[tid >> 5] = s;
    __syncthreads();
    float bs = red[0];
    #pragma unroll
    for (int i = 1; i < 8; i++) bs += red[i];
    float inv = 1.0f / bs;
    v.x *= inv; v.y *= inv; v.z *= inv; v.w *= inv;
    *(float4*)(p + tid * 4) = v;
}

// ---------------------------------------------------------------------------
// Launch
// ---------------------------------------------------------------------------
extern "C" void kernel_launch(void* const* d_in, const int* in_sizes, int n_in,
                              void* d_out, int out_size) {
    const float* x       = (const float*)d_in[0];
    const float* mask    = (const float*)d_in[1];
    const float* W_in    = (const float*)d_in[2];
    const float* W_rec   = (const float*)d_in[3];
    const float* b_lstm  = (const float*)d_in[4];
    const float* W_dense = (const float*)d_in[5];
    const float* b_dense = (const float*)d_in[6];
    float* out = (float*)d_out;

    float *xz, *hseq, *h0, *Wrec4, *b4;
    unsigned *bar, *q, *ready;
    __nv_bfloat16 *xh, *xl, *Wih, *Wil, *Wdh, *Wdl, *hh, *hl;
    cudaGetSymbolAddress((void**)&xz,    g_xz);
    cudaGetSymbolAddress((void**)&hseq,  g_hseq);
    cudaGetSymbolAddress((void**)&h0,    g_h0);
    cudaGetSymbolAddress((void**)&Wrec4, g_Wrec4);
    cudaGetSymbolAddress((void**)&b4,    g_b4);
    cudaGetSymbolAddress((void**)&bar,   g_bar);
    cudaGetSymbolAddress((void**)&q,     g_q);
    cudaGetSymbolAddress((void**)&ready, g_ready);
    cudaGetSymbolAddress((void**)&xh,    g_xh);
    cudaGetSymbolAddress((void**)&xl,    g_xl);
    cudaGetSymbolAddress((void**)&Wih,   g_Wih);
    cudaGetSymbolAddress((void**)&Wil,   g_Wil);
    cudaGetSymbolAddress((void**)&Wdh,   g_Wdh);
    cudaGetSymbolAddress((void**)&Wdl,   g_Wdl);
    cudaGetSymbolAddress((void**)&hh,    g_hh);
    cudaGetSymbolAddress((void**)&hl,    g_hl);

    cudaFuncSetAttribute(fused_p12,
                         cudaFuncAttributeMaxDynamicSharedMemorySize, FUSED_SMEM);
    cudaFuncSetAttribute(tgemm2,
                         cudaFuncAttributeMaxDynamicSharedMemorySize, GEMM_SMEM);

    // Pre-passes
    reorder_gates<<<(U_ * G4_ + 255) / 256, 256>>>(W_rec, Wrec4, U_ * G4_);
    reorder_split<<<(F_ * G4_ + 255) / 256, 256>>>(W_in, Wih, Wil, F_ * G4_);
    convert_split<<<(U_ * CODES_ / 4 + 255) / 256, 256>>>(W_dense, Wdh, Wdl, U_ * CODES_ / 4);
    convert_split<<<((int)((size_t)ROWS_ * F_ / 4) + 255) / 256, 256>>>(x, xh, xl, (int)((size_t)ROWS_ * F_ / 4));
    init_kernel<<<(B_ * U_ + 255) / 256, 256>>>(b_lstm, b4, h0, bar, q, ready);

    // Phase 1+2 fused
    fused_p12<<<RBLK, 512, FUSED_SMEM>>>(
        xh, xl, Wih, Wil, b4, xz, h0, Wrec4, hseq, bar, q, ready);

    // Phase 2.5: masked h -> bf16 hi/lo
    convert_mask<<<((int)((size_t)ROWS_ * U_ / 4) + 255) / 256, 256>>>(
        hseq, mask, hh, hl, (int)((size_t)ROWS_ * U_ / 4));

    // Phase 3: logits = relu(masked_h @ W_dense + b_dense)
    tgemm2<<<dim3(CODES_ / 128, ROWS_ / 128), 256, GEMM_SMEM>>>(
        hh, hl, Wdh, Wdl, b_dense, out, ROWS_, CODES_, U_, 1);

    // Phase 4: softmax
    softmax_kernel<<<ROWS_, 256>>>(out);
}

// round 11
// speedup vs baseline: 1.3582x; 1.0264x over previous
#include <cuda_runtime.h>
#include <cuda_bf16.h>
#include <math.h>
#include <stdint.h>

// Problem constants
#define T_   256
#define B_   128
#define F_   1024
#define U_   512
#define G4_  2048   // 4*U
#define CODES_ 1024
#define ROWS_ 32768 // T*B

#define RBLK 128    // fused persistent blocks (1/SM)
#define KC   64     // recurrence K chunk (was 32)
#define HPITCH 130  // Hs row pitch (even -> aligned 8B batch pairs)

// Tensor GEMM tile: 128x128, K-chunk 64
#define BKT  64
#define APITCH 72
#define BPITCH 136
#define SA_ELEM (128 * APITCH)                  // 9216
#define SB_ELEM (BKT * BPITCH)                  // 8704
#define STAGE_ELEM (2 * SA_ELEM + 2 * SB_ELEM)  // 35840
#define GEMM_SMEM (2 * STAGE_ELEM * 2)          // 143360 B

// Fused kernel smem layout (bytes)
#define FS_WS   GEMM_SMEM                        // 143360: W_rec slice (512x16 f32)
#define FS_HS   (FS_WS + 512 * 16 * 4)           // 176128: Hs (KC x HPITCH f32)
#define FS_TILE (FS_HS + KC * HPITCH * 4)        // 209408: tile broadcast slot
#define FUSED_SMEM (FS_TILE + 16)                // 209424

#define P1_TILES (T_ * (G4_ / 128))              // 4096 tiles, 16 per timestep

#define BARR1 asm volatile("bar.sync 1, 256;" ::: "memory")
#define BARR2 asm volatile("bar.sync 2, 256;" ::: "memory")

// ---------------------------------------------------------------------------
// Scratch
// ---------------------------------------------------------------------------
__device__ float g_xz   [(size_t)ROWS_ * G4_];
__device__ float g_hseq [(size_t)ROWS_ * U_];
__device__ float g_h0   [B_ * U_];
__device__ float g_Wrec4[(size_t)U_ * G4_];
__device__ float g_b4   [G4_];
__device__ unsigned g_bar;
__device__ unsigned g_q;
__device__ unsigned g_ready[T_];

__device__ __nv_bfloat16 g_xh [(size_t)ROWS_ * F_];
__device__ __nv_bfloat16 g_xl [(size_t)ROWS_ * F_];
__device__ __nv_bfloat16 g_Wih[(size_t)F_ * G4_];
__device__ __nv_bfloat16 g_Wil[(size_t)F_ * G4_];
__device__ __nv_bfloat16 g_Wdh[(size_t)U_ * CODES_];
__device__ __nv_bfloat16 g_Wdl[(size_t)U_ * CODES_];
__device__ __nv_bfloat16 g_hh [(size_t)ROWS_ * U_];
__device__ __nv_bfloat16 g_hl [(size_t)ROWS_ * U_];

// ---------------------------------------------------------------------------
// Helpers
// ---------------------------------------------------------------------------
__device__ __forceinline__ uint32_t smem_u32(const void* p) {
    return (uint32_t)__cvta_generic_to_shared(p);
}
__device__ __forceinline__ void cpa16(uint32_t dst, const void* src) {
    asm volatile("cp.async.cg.shared.global [%0], [%1], 16;\n" :: "r"(dst), "l"(src));
}
__device__ __forceinline__ void cpa_commit() { asm volatile("cp.async.commit_group;\n" ::); }
__device__ __forceinline__ void cpa_wait0()  { asm volatile("cp.async.wait_group 0;\n" ::); }
__device__ __forceinline__ void ldsm_x4(uint32_t& r0, uint32_t& r1, uint32_t& r2, uint32_t& r3, uint32_t a) {
    asm volatile("ldmatrix.sync.aligned.m8n8.x4.shared.b16 {%0,%1,%2,%3},[%4];"
                 : "=r"(r0), "=r"(r1), "=r"(r2), "=r"(r3) : "r"(a));
}
__device__ __forceinline__ void ldsm_x4t(uint32_t& r0, uint32_t& r1, uint32_t& r2, uint32_t& r3, uint32_t a) {
    asm volatile("ldmatrix.sync.aligned.m8n8.x4.trans.shared.b16 {%0,%1,%2,%3},[%4];"
                 : "=r"(r0), "=r"(r1), "=r"(r2), "=r"(r3) : "r"(a));
}
__device__ __forceinline__ void mma_bf16(float c[4], const uint32_t a[4], const uint32_t b[2]) {
    asm volatile(
        "mma.sync.aligned.m16n8k16.row.col.f32.bf16.bf16.f32 "
        "{%0,%1,%2,%3},{%4,%5,%6,%7},{%8,%9},{%0,%1,%2,%3};"
        : "+f"(c[0]), "+f"(c[1]), "+f"(c[2]), "+f"(c[3])
        : "r"(a[0]), "r"(a[1]), "r"(a[2]), "r"(a[3]), "r"(b[0]), "r"(b[1]));
}

// ---------------------------------------------------------------------------
// Pre-pass kernels
// ---------------------------------------------------------------------------
__global__ void reorder_gates(const float* __restrict__ W, float* __restrict__ W4, int total) {
    int idx = blockIdx.x * blockDim.x + threadIdx.x;
    if (idx >= total) return;
    int col = idx & (G4_ - 1);
    int k   = idx >> 11;
    W4[idx] = W[(size_t)k * G4_ + (col & 3) * U_ + (col >> 2)];
}

__global__ void reorder_split(const float* __restrict__ W,
                              __nv_bfloat16* __restrict__ hi,
                              __nv_bfloat16* __restrict__ lo, int total) {
    int idx = blockIdx.x * blockDim.x + threadIdx.x;
    if (idx >= total) return;
    int col = idx & (G4_ - 1);
    int k   = idx >> 11;
    float v = W[(size_t)k * G4_ + (col & 3) * U_ + (col >> 2)];
    __nv_bfloat16 h = __float2bfloat16(v);
    hi[idx] = h;
    lo[idx] = __float2bfloat16(v - __bfloat162float(h));
}

__global__ void convert_split(const float* __restrict__ src,
                              __nv_bfloat16* __restrict__ hi,
                              __nv_bfloat16* __restrict__ lo, int n4) {
    int idx = blockIdx.x * blockDim.x + threadIdx.x;
    if (idx >= n4) return;
    float4 v = *(const float4*)(src + (size_t)idx * 4);
    __nv_bfloat16 h0 = __float2bfloat16(v.x), h1 = __float2bfloat16(v.y);
    __nv_bfloat16 h2 = __float2bfloat16(v.z), h3 = __float2bfloat16(v.w);
    *(__nv_bfloat162*)(hi + (size_t)idx * 4)     = __halves2bfloat162(h0, h1);
    *(__nv_bfloat162*)(hi + (size_t)idx * 4 + 2) = __halves2bfloat162(h2, h3);
    *(__nv_bfloat162*)(lo + (size_t)idx * 4)     =
        __halves2bfloat162(__float2bfloat16(v.x - __bfloat162float(h0)),
                           __float2bfloat16(v.y - __bfloat162float(h1)));
    *(__nv_bfloat162*)(lo + (size_t)idx * 4 + 2) =
        __halves2bfloat162(__float2bfloat16(v.z - __bfloat162float(h2)),
                           __float2bfloat16(v.w - __bfloat162float(h3)));
}

__global__ void convert_mask(const float* __restrict__ hseq,
                             const float* __restrict__ mask,
                             __nv_bfloat16* __restrict__ hi,
                             __nv_bfloat16* __restrict__ lo, int n4) {
    int idx = blockIdx.x * blockDim.x + threadIdx.x;
    if (idx >= n4) return;
    float m = mask[(idx * 4) >> 9];
    float4 v = *(const float4*)(hseq + (size_t)idx * 4);
    v.x *= m; v.y *= m; v.z *= m; v.w *= m;
    __nv_bfloat16 h0 = __float2bfloat16(v.x), h1 = __float2bfloat16(v.y);
    __nv_bfloat16 h2 = __float2bfloat16(v.z), h3 = __float2bfloat16(v.w);
    *(__nv_bfloat162*)(hi + (size_t)idx * 4)     = __halves2bfloat162(h0, h1);
    *(__nv_bfloat162*)(hi + (size_t)idx * 4 + 2) = __halves2bfloat162(h2, h3);
    *(__nv_bfloat162*)(lo + (size_t)idx * 4)     =
        __halves2bfloat162(__float2bfloat16(v.x - __bfloat162float(h0)),
                           __float2bfloat16(v.y - __bfloat162float(h1)));
    *(__nv_bfloat162*)(lo + (size_t)idx * 4 + 2) =
        __halves2bfloat162(__float2bfloat16(v.z - __bfloat162float(h2)),
                           __float2bfloat16(v.w - __bfloat162float(h3)));
}

__global__ void init_kernel(const float* __restrict__ b_lstm,
                            float* __restrict__ b4,
                            float* __restrict__ h0,
                            unsigned* __restrict__ bar,
                            unsigned* __restrict__ q,
                            unsigned* __restrict__ ready) {
    int idx = blockIdx.x * blockDim.x + threadIdx.x;
    if (idx == 0) { *bar = 0u; *q = 0u; }
    if (idx < T_) ready[idx] = 0u;
    if (idx < G4_) b4[idx] = b_lstm[(idx & 3) * U_ + (idx >> 2)];
    if (idx < B_ * U_) h0[idx] = 0.0f;
}

// ---------------------------------------------------------------------------
// Stand-alone tensor GEMM (BKT=64) for phase 3.
// ---------------------------------------------------------------------------
__global__ __launch_bounds__(256, 1) void tgemm2(
    const __nv_bfloat16* __restrict__ Ah, const __nv_bfloat16* __restrict__ Al,
    const __nv_bfloat16* __restrict__ Bh, const __nv_bfloat16* __restrict__ Bl,
    const float* __restrict__ bias, float* __restrict__ C,
    int M, int N, int K, int relu)
{
    extern __shared__ __nv_bfloat16 ts[];

    int tid  = threadIdx.x;
    int warp = tid >> 5, lane = tid & 31;
    int wm = warp >> 1, wn = warp & 1;
    int m0 = blockIdx.y * 128, n0 = blockIdx.x * 128;

    float acc[2][8][4];
    #pragma unroll
    for (int i = 0; i < 2; i++)
        #pragma unroll
        for (int j = 0; j < 8; j++)
            #pragma unroll
            for (int q = 0; q < 4; q++) acc[i][j][q] = 0.0f;

    int a_r = (lane & 15);
    int a_c = (lane >> 4) * 8;
    int aoffA = (wm * 32 + a_r) * APITCH + a_c;
    int aoffB = a_r * BPITCH + wn * 64 + a_c;

    int KT = K / BKT;

    auto load_stage = [&](int kt, int s) {
        __nv_bfloat16* st = ts + s * STAGE_ELEM;
        __nv_bfloat16* sAh = st;
        __nv_bfloat16* sAl = st + SA_ELEM;
        __nv_bfloat16* sBh = st + 2 * SA_ELEM;
        __nv_bfloat16* sBl = st + 2 * SA_ELEM + SB_ELEM;
        int k0 = kt * BKT;
        const __nv_bfloat16* gAh = Ah + (size_t)m0 * K + k0;
        const __nv_bfloat16* gAl = Al + (size_t)m0 * K + k0;
        const __nv_bfloat16* gBh = Bh + (size_t)k0 * N + n0;
        const __nv_bfloat16* gBl = Bl + (size_t)k0 * N + n0;
        #pragma unroll
        for (int j = 0; j < 4; j++) {
            int ca = tid + j * 256;
            int ar = ca >> 3, as = ca & 7;
            cpa16(smem_u32(sAh + ar * APITCH + as * 8), gAh + (size_t)ar * K + as * 8);
            cpa16(smem_u32(sAl + ar * APITCH + as * 8), gAl + (size_t)ar * K + as * 8);
            int cb = tid + j * 256;
            int br = cb >> 4, bs = cb & 15;
            cpa16(smem_u32(sBh + br * BPITCH + bs * 8), gBh + (size_t)br * N + bs * 8);
            cpa16(smem_u32(sBl + br * BPITCH + bs * 8), gBl + (size_t)br * N + bs * 8);
        }
    };

    load_stage(0, 0);
    cpa_commit();
    cpa_wait0();
    __syncthreads();

    for (int kt = 0; kt < KT; kt++) {
        int cur = kt & 1;
        if (kt + 1 < KT) {
            load_stage(kt + 1, cur ^ 1);
            cpa_commit();
        }

        __nv_bfloat16* st = ts + cur * STAGE_ELEM;
        uint32_t aAh = smem_u32(st + aoffA);
        uint32_t aAl = smem_u32(st + SA_ELEM + aoffA);
        uint32_t aBh = smem_u32(st + 2 * SA_ELEM + aoffB);
        uint32_t aBl = smem_u32(st + 2 * SA_ELEM + SB_ELEM + aoffB);

        #pragma unroll
        for (int kk = 0; kk < 4; kk++) {
            uint32_t Ahf[2][4], Alf[2][4];
            #pragma unroll
            for (int mt = 0; mt < 2; mt++) {
                uint32_t off = (mt * 16) * APITCH * 2 + kk * 16 * 2;
                ldsm_x4(Ahf[mt][0], Ahf[mt][1], Ahf[mt][2], Ahf[mt][3], aAh + off);
                ldsm_x4(Alf[mt][0], Alf[mt][1], Alf[mt][2], Alf[mt][3], aAl + off);
            }
            uint32_t Bhf[8][2], Blf[8][2];
            #pragma unroll
            for (int p = 0; p < 4; p++) {
                uint32_t off = (kk * 16) * BPITCH * 2 + p * 16 * 2;
                ldsm_x4t(Bhf[2*p][0], Bhf[2*p][1], Bhf[2*p+1][0], Bhf[2*p+1][1], aBh + off);
                ldsm_x4t(Blf[2*p][0], Blf[2*p][1], Blf[2*p+1][0], Blf[2*p+1][1], aBl + off);
            }
            #pragma unroll
            for (int mt = 0; mt < 2; mt++)
                #pragma unroll
                for (int nt = 0; nt < 8; nt++) {
                    mma_bf16(acc[mt][nt], Ahf[mt], Bhf[nt]);
                    mma_bf16(acc[mt][nt], Ahf[mt], Blf[nt]);
                    mma_bf16(acc[mt][nt], Alf[mt], Bhf[nt]);
                }
        }

        if (kt + 1 < KT) cpa_wait0();
        __syncthreads();
    }

    int crow = lane >> 2;
    int ccol = (lane & 3) * 2;
    #pragma unroll
    for (int mt = 0; mt < 2; mt++) {
        int r0 = m0 + wm * 32 + mt * 16 + crow;
        #pragma unroll
        for (int nt = 0; nt < 8; nt++) {
            int cglob = n0 + wn * 64 + nt * 8 + ccol;
            float b0 = bias[cglob], b1 = bias[cglob + 1];
            float2 v0 = { acc[mt][nt][0] + b0, acc[mt][nt][1] + b1 };
            float2 v1 = { acc[mt][nt][2] + b0, acc[mt][nt][3] + b1 };
            if (relu) {
                v0.x = fmaxf(v0.x, 0.f); v0.y = fmaxf(v0.y, 0.f);
                v1.x = fmaxf(v1.x, 0.f); v1.y = fmaxf(v1.y, 0.f);
            }
            *(float2*)(C + (size_t)r0 * N + cglob)       = v0;
            *(float2*)(C + (size_t)(r0 + 8) * N + cglob) = v1;
        }
    }
}

// ---------------------------------------------------------------------------
// FUSED phase1+phase2. GEMM role unchanged (BKT=64). Recurrence role:
// KC=64 (half the barriers), Hs pitch 130 (even) so the (b,b+1) pair reads
// as ONE aligned LDS.64 -> inner kk is 2 shared loads instead of 3.
// ---------------------------------------------------------------------------
__global__ __launch_bounds__(512, 1) void fused_p12(
    const __nv_bfloat16* __restrict__ Ah, const __nv_bfloat16* __restrict__ Al,
    const __nv_bfloat16* __restrict__ Bh, const __nv_bfloat16* __restrict__ Bl,
    const float* __restrict__ b4, float* xz,
    const float* __restrict__ h0, const float* __restrict__ Wrec,
    float* hseq, unsigned* bar, unsigned* q, unsigned* ready)
{
    extern __shared__ char smemc[];
    int tid = threadIdx.x;

    if (tid < 256) {
        // ------------------ RECURRENCE ROLE (bar 1) -----------------------
        float* Ws = (float*)(smemc + FS_WS);     // [512][16]
        float* Hs = (float*)(smemc + FS_HS);     // [KC][HPITCH]
        int rtid = tid;
        int blk = blockIdx.x;
        int n0 = blk * 16;
        int tx = rtid & 3;
        int ty = rtid >> 2;
        int u  = blk * 4 + tx;

        for (int l = rtid; l < 512 * 4; l += 256) {
            int row = l >> 2, c4 = l & 3;
            *(float4*)&Ws[row * 16 + c4 * 4] =
                *(const float4*)(Wrec + (size_t)row * G4_ + n0 + c4 * 4);
        }

        float creg0 = 0.0f, creg1 = 0.0f;
        const float* hp = h0;

        for (int t = 0; t < T_; t++) {
            float acc[2][4];
            #pragma unroll
            for (int i = 0; i < 2; i++)
                #pragma unroll
                for (int j = 0; j < 4; j++) acc[i][j] = 0.0f;

            for (int k0 = 0; k0 < U_; k0 += KC) {
                // stage h chunk transposed: Hs[kk][b], pitch HPITCH (even)
                #pragma unroll
                for (int i = 0; i < 8; i++) {
                    int l = rtid + i * 256;         // 0..2047 float4
                    int b = l >> 4, k4 = l & 15;
                    float4 v = __ldcg((const float4*)(hp + (size_t)b * U_ + k0 + k4 * 4));
                    Hs[(k4 * 4 + 0) * HPITCH + b] = v.x;
                    Hs[(k4 * 4 + 1) * HPITCH + b] = v.y;
                    Hs[(k4 * 4 + 2) * HPITCH + b] = v.z;
                    Hs[(k4 * 4 + 3) * HPITCH + b] = v.w;
                }
                BARR1;

                #pragma unroll 16
                for (int kk = 0; kk < KC; kk++) {
                    float4 wv = *(float4*)&Ws[(k0 + kk) * 16 + tx * 4];
                    float2 hv = *(float2*)&Hs[kk * HPITCH + ty * 2];
                    acc[0][0] += hv.x * wv.x; acc[0][1] += hv.x * wv.y;
                    acc[0][2] += hv.x * wv.z; acc[0][3] += hv.x * wv.w;
                    acc[1][0] += hv.y * wv.x; acc[1][1] += hv.y * wv.y;
                    acc[1][2] += hv.y * wv.z; acc[1][3] += hv.y * wv.w;
                }
                BARR1;
            }

            if (rtid == 0) {
                while (((volatile unsigned*)ready)[t] < 16u) {}
                __threadfence();
            }
            BARR1;

            #pragma unroll
            for (int i = 0; i < 2; i++) {
                int b = ty * 2 + i;
                const float4* xzp = (const float4*)(xz + ((size_t)t * B_ + b) * G4_ + n0 + tx * 4);
                float4 xv = __ldcg(xzp);
                float zi = acc[i][0] + xv.x;
                float zf = acc[i][1] + xv.y;
                float zg = acc[i][2] + xv.z;
                float zo = acc[i][3] + xv.w;
                float ig = 1.0f / (1.0f + expf(-zi));
                float fg = 1.0f / (1.0f + expf(-zf));
                float gg = tanhf(zg);
                float og = 1.0f / (1.0f + expf(-zo));
                float cp = i ? creg1 : creg0;
                float cn = fg * cp + ig * gg;
                if (i) creg1 = cn; else creg0 = cn;
                hseq[((size_t)t * B_ + b) * U_ + u] = og * tanhf(cn);
            }

            __threadfence();
            BARR1;
            if (rtid == 0) {
                atomicAdd(bar, 1u);
                unsigned target = (unsigned)RBLK * (unsigned)(t + 1);
                while (*(volatile unsigned*)bar < target) {}
            }
            BARR1;

            hp = hseq + (size_t)t * B_ * U_;
        }
    } else {
        // ------------------ GEMM ROLE (phase 1, BKT=64, bar 2) ------------
        __nv_bfloat16* ts = (__nv_bfloat16*)smemc;
        volatile int* sm_tile = (volatile int*)(smemc + FS_TILE);
        int wtid = tid - 256;
        int warp = wtid >> 5, lane = wtid & 31;
        int wm = warp >> 1, wn = warp & 1;

        int a_r = (lane & 15);
        int a_c = (lane >> 4) * 8;
        int aoffA = (wm * 32 + a_r) * APITCH + a_c;
        int aoffB = a_r * BPITCH + wn * 64 + a_c;

        const int Kg = F_, Ng = G4_, KT = F_ / BKT;

        for (;;) {
            if (wtid == 0) *sm_tile = (int)atomicAdd(q, 1u);
            BARR2;
            int tile = *sm_tile;
            BARR2;
            if (tile >= P1_TILES) break;
            int m0 = (tile >> 4) * 128;     // t-major: tile = t*16 + ncol
            int n0 = (tile & 15) * 128;

            float acc[2][8][4];
            #pragma unroll
            for (int i = 0; i < 2; i++)
                #pragma unroll
                for (int j = 0; j < 8; j++)
                    #pragma unroll
                    for (int qq = 0; qq < 4; qq++) acc[i][j][qq] = 0.0f;

            auto load_stage = [&](int kt, int s) {
                __nv_bfloat16* st = ts + s * STAGE_ELEM;
                __nv_bfloat16* sAh = st;
                __nv_bfloat16* sAl = st + SA_ELEM;
                __nv_bfloat16* sBh = st + 2 * SA_ELEM;
                __nv_bfloat16* sBl = st + 2 * SA_ELEM + SB_ELEM;
                int k0 = kt * BKT;
                const __nv_bfloat16* gAh = Ah + (size_t)m0 * Kg + k0;
                const __nv_bfloat16* gAl = Al + (size_t)m0 * Kg + k0;
                const __nv_bfloat16* gBh = Bh + (size_t)k0 * Ng + n0;
                const __nv_bfloat16* gBl = Bl + (size_t)k0 * Ng + n0;
                #pragma unroll
                for (int j = 0; j < 4; j++) {
                    int ca = wtid + j * 256;
                    int ar = ca >> 3, as = ca & 7;
                    cpa16(smem_u32(sAh + ar * APITCH + as * 8), gAh + (size_t)ar * Kg + as * 8);
                    cpa16(smem_u32(sAl + ar * APITCH + as * 8), gAl + (size_t)ar * Kg + as * 8);
                    int cb = wtid + j * 256;
                    int br = cb >> 4, bs = cb & 15;
                    cpa16(smem_u32(sBh + br * BPITCH + bs * 8), gBh + (size_t)br * Ng + bs * 8);
                    cpa16(smem_u32(sBl + br * BPITCH + bs * 8), gBl + (size_t)br * Ng + bs * 8);
                }
            };

            load_stage(0, 0);
            cpa_commit();
            cpa_wait0();
            BARR2;

            for (int kt = 0; kt < KT; kt++) {
                int cur = kt & 1;
                if (kt + 1 < KT) {
                    load_stage(kt + 1, cur ^ 1);
                    cpa_commit();
                }

                __nv_bfloat16* st = ts + cur * STAGE_ELEM;
                uint32_t aAh = smem_u32(st + aoffA);
                uint32_t aAl = smem_u32(st + SA_ELEM + aoffA);
                uint32_t aBh = smem_u32(st + 2 * SA_ELEM + aoffB);
                uint32_t aBl = smem_u32(st + 2 * SA_ELEM + SB_ELEM + aoffB);

                #pragma unroll
                for (int kk = 0; kk < 4; kk++) {
                    uint32_t Ahf[2][4], Alf[2][4];
                    #pragma unroll
                    for (int mt = 0; mt < 2; mt++) {
                        uint32_t off = (mt * 16) * APITCH * 2 + kk * 16 * 2;
                        ldsm_x4(Ahf[mt][0], Ahf[mt][1], Ahf[mt][2], Ahf[mt][3], aAh + off);
                        ldsm_x4(Alf[mt][0], Alf[mt][1], Alf[mt][2], Alf[mt][3], aAl + off);
                    }
                    uint32_t Bhf[8][2], Blf[8][2];
                    #pragma unroll
                    for (int p = 0; p < 4; p++) {
                        uint32_t off = (kk * 16) * BPITCH * 2 + p * 16 * 2;
                        ldsm_x4t(Bhf[2*p][0], Bhf[2*p][1], Bhf[2*p+1][0], Bhf[2*p+1][1], aBh + off);
                        ldsm_x4t(Blf[2*p][0], Blf[2*p][1], Blf[2*p+1][0], Blf[2*p+1][1], aBl + off);
                    }
                    #pragma unroll
                    for (int mt = 0; mt < 2; mt++)
                        #pragma unroll
                        for (int nt = 0; nt < 8; nt++) {
                            mma_bf16(acc[mt][nt], Ahf[mt], Bhf[nt]);
                            mma_bf16(acc[mt][nt], Ahf[mt], Blf[nt]);
                            mma_bf16(acc[mt][nt], Alf[mt], Bhf[nt]);
                        }
                }

                if (kt + 1 < KT) cpa_wait0();
                BARR2;
            }

            int crow = lane >> 2;
            int ccol = (lane & 3) * 2;
            #pragma unroll
            for (int mt = 0; mt < 2; mt++) {
                int r0 = m0 + wm * 32 + mt * 16 + crow;
                #pragma unroll
                for (int nt = 0; nt < 8; nt++) {
                    int cglob = n0 + wn * 64 + nt * 8 + ccol;
                    float b0 = b4[cglob], b1 = b4[cglob + 1];
                    float2 v0 = { acc[mt][nt][0] + b0, acc[mt][nt][1] + b1 };
                    float2 v1 = { acc[mt][nt][2] + b0, acc[mt][nt][3] + b1 };
                    *(float2*)(xz + (size_t)r0 * Ng + cglob)       = v0;
                    *(float2*)(xz + (size_t)(r0 + 8) * Ng + cglob) = v1;
                }
            }

            __threadfence();
            BARR2;
            if (wtid == 0) atomicAdd(ready + (m0 >> 7), 1u);
        }
    }
}

// ---------------------------------------------------------------------------
// In-place row softmax (1024 cols, one block/row).
// ---------------------------------------------------------------------------
__global__ __launch_bounds__(256) void softmax_kernel(float* __restrict__ out) {
    __shared__ float red[8];
    int tid = threadIdx.x;
    float* p = out + (size_t)blockIdx.x * CODES_;

    float4 v = *(float4*)(p + tid * 4);
    float m = fmaxf(fmaxf(v.x, v.y), fmaxf(v.z, v.w));
    #pragma unroll
    for (int o = 16; o > 0; o >>= 1) m = fmaxf(m, __shfl_xor_sync(0xFFFFFFFFu, m, o));
    if ((tid & 31) == 0) red[tid >> 5] = m;
    __syncthreads();
    float bm = red[0];
    #pragma unroll
    for (int i = 1; i < 8; i++) bm = fmaxf(bm, red[i]);
    __syncthreads();

    v.x = expf(v.x - bm); v.y = expf(v.y - bm);
    v.z = expf(v.z - bm); v.w = expf(v.w - bm);
    float s = v.x + v.y + v.z + v.w;
    #pragma unroll
    for (int o = 16; o > 0; o >>= 1) s += __shfl_xor_sync(0xFFFFFFFFu, s, o);
    if ((tid & 31) == 0) red[tid >> 5] = s;
    __syncthreads();
    float bs = red[0];
    #pragma unroll
    for (int i = 1; i < 8; i++) bs += red[i];
    float inv = 1.0f / bs;
    v.x *= inv; v.y *= inv; v.z *= inv; v.w *= inv;
    *(float4*)(p + tid * 4) = v;
}

// ---------------------------------------------------------------------------
// Launch
// ---------------------------------------------------------------------------
extern "C" void kernel_launch(void* const* d_in, const int* in_sizes, int n_in,
                              void* d_out, int out_size) {
    const float* x       = (const float*)d_in[0];
    const float* mask    = (const float*)d_in[1];
    const float* W_in    = (const float*)d_in[2];
    const float* W_rec   = (const float*)d_in[3];
    const float* b_lstm  = (const float*)d_in[4];
    const float* W_dense = (const float*)d_in[5];
    const float* b_dense = (const float*)d_in[6];
    float* out = (float*)d_out;

    float *xz, *hseq, *h0, *Wrec4, *b4;
    unsigned *bar, *q, *ready;
    __nv_bfloat16 *xh, *xl, *Wih, *Wil, *Wdh, *Wdl, *hh, *hl;
    cudaGetSymbolAddress((void**)&xz,    g_xz);
    cudaGetSymbolAddress((void**)&hseq,  g_hseq);
    cudaGetSymbolAddress((void**)&h0,    g_h0);
    cudaGetSymbolAddress((void**)&Wrec4, g_Wrec4);
    cudaGetSymbolAddress((void**)&b4,    g_b4);
    cudaGetSymbolAddress((void**)&bar,   g_bar);
    cudaGetSymbolAddress((void**)&q,     g_q);
    cudaGetSymbolAddress((void**)&ready, g_ready);
    cudaGetSymbolAddress((void**)&xh,    g_xh);
    cudaGetSymbolAddress((void**)&xl,    g_xl);
    cudaGetSymbolAddress((void**)&Wih,   g_Wih);
    cudaGetSymbolAddress((void**)&Wil,   g_Wil);
    cudaGetSymbolAddress((void**)&Wdh,   g_Wdh);
    cudaGetSymbolAddress((void**)&Wdl,   g_Wdl);
    cudaGetSymbolAddress((void**)&hh,    g_hh);
    cudaGetSymbolAddress((void**)&hl,    g_hl);

    cudaFuncSetAttribute(fused_p12,
                         cudaFuncAttributeMaxDynamicSharedMemorySize, FUSED_SMEM);
    cudaFuncSetAttribute(tgemm2,
                         cudaFuncAttributeMaxDynamicSharedMemorySize, GEMM_SMEM);

    // Pre-passes
    reorder_gates<<<(U_ * G4_ + 255) / 256, 256>>>(W_rec, Wrec4, U_ * G4_);
    reorder_split<<<(F_ * G4_ + 255) / 256, 256>>>(W_in, Wih, Wil, F_ * G4_);
    convert_split<<<(U_ * CODES_ / 4 + 255) / 256, 256>>>(W_dense, Wdh, Wdl, U_ * CODES_ / 4);
    convert_split<<<((int)((size_t)ROWS_ * F_ / 4) + 255) / 256, 256>>>(x, xh, xl, (int)((size_t)ROWS_ * F_ / 4));
    init_kernel<<<(B_ * U_ + 255) / 256, 256>>>(b_lstm, b4, h0, bar, q, ready);

    // Phase 1+2 fused
    fused_p12<<<RBLK, 512, FUSED_SMEM>>>(
        xh, xl, Wih, Wil, b4, xz, h0, Wrec4, hseq, bar, q, ready);

    // Phase 2.5: masked h -> bf16 hi/lo
    convert_mask<<<((int)((size_t)ROWS_ * U_ / 4) + 255) / 256, 256>>>(
        hseq, mask, hh, hl, (int)((size_t)ROWS_ * U_ / 4));

    // Phase 3: logits = relu(masked_h @ W_dense + b_dense)
    tgemm2<<<dim3(CODES_ / 128, ROWS_ / 128), 256, GEMM_SMEM>>>(
        hh, hl, Wdh, Wdl, b_dense, out, ROWS_, CODES_, U_, 1);

    // Phase 4: softmax
    softmax_kernel<<<ROWS_, 256>>>(out);
}